// round 5
// baseline (speedup 1.0000x reference)
#include <cuda_runtime.h>
#include <math.h>

#define Bq 2
#define NEGq 16
#define Nn 10000
#define Ee 80000
#define Dd 128
#define NUMREL 237
#define Lq 3
#define Kq 1000
#define BNq (Bq*Nn)
#define BEq (Bq*Ee)
#define EPSq 1e-5f
#define NBLK ((BNq+1023)/1024)

typedef unsigned long long ull;

// ----------------- persistent device scratch (no allocations) -----------------
__device__ float g_hidden[BNq*Dd];
__device__ float g_score[BNq];
__device__ unsigned char g_sel[BNq];
__device__ int   g_outdeg[BNq];
__device__ int   g_soutdeg[BNq];     // static out-degree (full edge set)
__device__ int   g_indeg[BNq];       // CSR count / fill cursor
__device__ int   g_rowptr[BNq+1];
__device__ int   g_col[BEq];         // CSR-by-dst: src flat ids
__device__ float g_utab[BNq*Dd];     // A·h, node-indexed (valid iff touched)
__device__ float g_vtab[BNq*Dd];     // B·h, node-indexed (valid iff touched)
__device__ int   g_gatedB[Bq*Nn];    // per-batch gated lists (offset b*Nn)
__device__ int   g_ngatedB[Bq];
__device__ int   g_touchedlist[BNq];
__device__ unsigned char g_touched[BNq];
__device__ float g_rel[Bq*Dd];
__device__ float g_relc[Bq*Dd];      // linb + rel @ linW[D:2D]
__device__ float g_hvals[Bq*Dd];
__device__ float g_tvals[Bq*Dd];
__device__ int   g_flat_h[Bq];
__device__ int   g_flat_t[Bq];
__device__ int   g_tgather[Bq*NEGq];
__device__ int   g_ntouched;
__device__ float g_avgpart[Bq];
__device__ float g_c0;
__device__ int   g_btot[NBLK];
__device__ int   g_boff[NBLK];

// order-preserving encoding for float ranking
__device__ __forceinline__ unsigned fenc(float f){
    unsigned u = __float_as_uint(f);
    return (u & 0x80000000u) ? ~u : (u | 0x80000000u);
}

// ----- packed f32x2 helpers (sm_103a FFMA2) -----
__device__ __forceinline__ ull f2pk(float lo, float hi){
    ull r; asm("mov.b64 %0, {%1,%2};" : "=l"(r) : "f"(lo), "f"(hi)); return r;
}
__device__ __forceinline__ ull f2dup(float w){ return f2pk(w,w); }
__device__ __forceinline__ void fma2(ull &d, ull a, ull b){
    asm("fma.rn.f32x2 %0, %1, %2, %0;" : "+l"(d) : "l"(a), "l"(b));
}
__device__ __forceinline__ float2 f2up(ull v){
    float lo, hi; asm("mov.b64 {%0,%1}, %2;" : "=f"(lo), "=f"(hi) : "l"(v));
    return make_float2(lo,hi);
}

// ----------------- setup -----------------
__global__ void k_setup(const int* h_index, const int* r_index, const int* t_index,
                        const float* hidden_states, const float* rel_embedding,
                        const float* m1_b, const float* m2_W, const float* m2_b){
    __shared__ int sh_h0[Bq], sh_t0[Bq], sh_r0[Bq], sh_neg[Bq];
    int tid = threadIdx.x;
    if (tid < Bq){
        int b = tid;
        int h0 = h_index[b*NEGq];
        int neg = 1;
        for (int j=1;j<NEGq;j++) if (h_index[b*NEGq+j]!=h0) neg=0;
        int hh = neg ? h0 : t_index[b*NEGq];
        int tt = neg ? t_index[b*NEGq] : h0;
        int rr = neg ? r_index[b*NEGq] : r_index[b*NEGq] + NUMREL;
        sh_h0[b]=hh; sh_t0[b]=tt; sh_r0[b]=rr; sh_neg[b]=neg;
        g_flat_h[b] = hh + b*Nn;
        g_flat_t[b] = tt + b*Nn;
    }
    if (tid==0){ g_ntouched = 0; }
    __syncthreads();
    for (int idx=tid; idx<Bq*NEGq; idx+=blockDim.x){
        int b = idx/NEGq;
        int tv = sh_neg[b] ? t_index[idx] : h_index[idx];
        g_tgather[idx] = tv + b*Nn;
    }
    for (int idx=tid; idx<Bq*Dd; idx+=blockDim.x){
        int b = idx/Dd; int d = idx - b*Dd;
        g_rel[idx] = rel_embedding[sh_r0[b]*Dd + d];
        int selb = b / Nn;   // literal repeat_interleave(N)[:B] quirk -> 0
        g_hvals[idx] = hidden_states[sh_h0[selb]*Dd + d];
        g_tvals[idx] = hidden_states[sh_t0[selb]*Dd + d];
    }
    if (tid==0){
        float acc = 0.f;
        for (int d=0; d<Dd; d++){ float h = fmaxf(m1_b[d],0.f); acc += h*m2_W[d]; }
        g_c0 = acc + m2_b[0];
    }
}

__global__ void k_clear_state(){
    int gid = blockIdx.x*blockDim.x + threadIdx.x;
    int stride = gridDim.x*blockDim.x;
    for (int i=gid; i<BNq*Dd; i+=stride) g_hidden[i] = 0.f;
    for (int i=gid; i<BNq; i+=stride){
        g_score[i]=0.f; g_touched[i]=0;
        g_indeg[i]=0; g_soutdeg[i]=0;
    }
}

// ----------------- static CSR-by-dst build -----------------
__global__ void k_csr_count(const int* edge_index){
    int gid = blockIdx.x*blockDim.x + threadIdx.x;
    int stride = gridDim.x*blockDim.x;
    for (int e=gid; e<BEq; e+=stride){
        int b = e / Ee; int ei = e - b*Ee;
        int s = edge_index[ei] + b*Nn;
        int d = edge_index[Ee + ei] + b*Nn;
        atomicAdd(&g_indeg[d], 1);
        atomicAdd(&g_soutdeg[s], 1);
    }
}

__global__ void k_scanA(){
    __shared__ int ws[32];
    int b=blockIdx.x, tid=threadIdx.x, lane=tid&31, wid=tid>>5;
    int i=b*1024+tid;
    int c=(i<BNq)? g_indeg[i]:0;
    int inc=c;
    for(int o=1;o<32;o<<=1){int n=__shfl_up_sync(0xffffffffu,inc,o); if(lane>=o) inc+=n;}
    if(lane==31) ws[wid]=inc;
    __syncthreads();
    if(wid==0){
        int v=ws[lane], iv=v;
        for(int o=1;o<32;o<<=1){int n=__shfl_up_sync(0xffffffffu,iv,o); if(lane>=o) iv+=n;}
        ws[lane]=iv-v;
    }
    __syncthreads();
    int excl=ws[wid]+inc-c;
    if(i<BNq) g_rowptr[i]=excl;
    if(tid==1023) g_btot[b]=excl+c;
}

__global__ void k_scanB(){
    int lane=threadIdx.x;
    int v=(lane<NBLK)? g_btot[lane]:0;
    int iv=v;
    for(int o=1;o<32;o<<=1){int n=__shfl_up_sync(0xffffffffu,iv,o); if(lane>=o) iv+=n;}
    if(lane<NBLK) g_boff[lane]=iv-v;
    if(lane==0) g_rowptr[BNq]=BEq;
}

__global__ void k_scanC(){
    int b=blockIdx.x, tid=threadIdx.x;
    int i=b*1024+tid;
    if(i<BNq){
        int r=g_rowptr[i]+g_boff[b];
        g_rowptr[i]=r;
        g_indeg[i]=r;   // fill cursor
    }
}

__global__ void k_csr_fill(const int* edge_index){
    int gid = blockIdx.x*blockDim.x + threadIdx.x;
    int stride = gridDim.x*blockDim.x;
    for (int e=gid; e<BEq; e+=stride){
        int b = e / Ee; int ei = e - b*Ee;
        int s = edge_index[ei] + b*Nn;
        int d = edge_index[Ee + ei] + b*Nn;
        int pos = atomicAdd(&g_indeg[d], 1);
        g_col[pos] = s;
    }
}

__global__ void k_boundary(){
    int b = blockIdx.x, d = threadIdx.x;
    int fh = g_flat_h[b], ft = g_flat_t[b];
    if (ft != fh) g_hidden[ft*Dd + d] = g_tvals[b*Dd + d];
    g_hidden[fh*Dd + d] = g_hvals[b*Dd + d];
    if (d==0){
        int p = atomicAdd(&g_ntouched,1); g_touchedlist[p]=fh; g_touched[fh]=1;
        if (ft != fh){ p = atomicAdd(&g_ntouched,1); g_touchedlist[p]=ft; g_touched[ft]=1; }
    }
}

// relc = linb + rel @ linW[D:2D]; head init score
__global__ void k_init_relc_score(const float* linW, const float* linb,
                                  const float* m1W, const float* m1b,
                                  const float* m2W, const float* m2b){
    __shared__ float shv[Dd], srl[Dd], sx[Dd], sp[Dd];
    int b = blockIdx.x, d = threadIdx.x;
    shv[d] = g_hvals[b*Dd + d];
    srl[d] = g_rel[b*Dd + d];
    __syncthreads();
    float rc = linb[d];
    for (int k=0;k<Dd;k++) rc += srl[k]*linW[(Dd+k)*Dd + d];
    g_relc[b*Dd + d] = rc;
    float acc = rc;
    for (int k=0;k<Dd;k++) acc += shv[k]*linW[k*Dd + d];
    sx[d] = acc * shv[d];
    __syncthreads();
    float h = m1b[d];
    for (int k=0;k<Dd;k++) h += sx[k]*m1W[k*Dd + d];
    sp[d] = fmaxf(h, 0.f) * m2W[d];
    __syncthreads();
    if (d==0){
        float s=0.f; for (int k=0;k<Dd;k++) s += sp[k];
        g_score[g_flat_h[b]] = s + m2b[0];
    }
}

// ----------------- fused select + mark + deg/gated/touched/prefill/avglog -----------------
__global__ void k_selmark(int layer){
    __shared__ unsigned hist[4096];
    __shared__ unsigned warpSum[32];
    __shared__ unsigned sPrefix, sG;
    __shared__ int wexcl[32];
    __shared__ int running, chunktot;
    __shared__ float wlog[32];
    int batch = blockIdx.x;
    int tid = threadIdx.x, lane=tid&31, wid=tid>>5;
    const float* sc = g_score + batch*Nn;
    if (tid==0){ sPrefix=0u; sG=0u; running=0; g_ngatedB[batch]=0; }
    __syncthreads();
    // 3-pass radix select (12/12/8 bits)
    for (int lvl=0;lvl<3;lvl++){
        for (int i=tid;i<4096;i+=1024) hist[i]=0u;
        __syncthreads();
        unsigned p=sPrefix;
        for (int i=tid;i<Nn;i+=1024){
            unsigned e=fenc(sc[i]); unsigned key; bool ok;
            if(lvl==0){ ok=true;              key=e>>20; }
            else if(lvl==1){ ok=((e>>20)==p); key=(e>>8)&0xFFFu; }
            else           { ok=((e>>8)==p);  key=e&0xFFu; }
            if(ok) atomicAdd(&hist[key],1u);
        }
        __syncthreads();
        unsigned v=hist[tid*4]+hist[tid*4+1]+hist[tid*4+2]+hist[tid*4+3];
        for(int o=16;o>0;o>>=1) v+=__shfl_down_sync(0xffffffffu,v,o);
        if(lane==0) warpSum[wid]=v;
        __syncthreads();
        if(tid==0){
            unsigned R=(unsigned)Kq - sG;
            unsigned acc=0; int beta=0;
            for(int w=31;w>=0;w--){
                if(acc+warpSum[w]>=R){
                    for(int b2=w*128+127;b2>=w*128;b2--){
                        if(acc+hist[b2]>=R){ beta=b2; break; }
                        acc+=hist[b2];
                    }
                    break;
                }
                acc+=warpSum[w];
            }
            sG+=acc;
            sPrefix=(lvl==0)?(unsigned)beta:((sPrefix<<((lvl==1)?12:8))|(unsigned)beta);
        }
        __syncthreads();
    }
    unsigned T=sPrefix; int R=Kq-(int)sG;
    // mark: > T always; == T first R by ascending index (jax top_k tie order)
    for(int start=0;start<Nn;start+=1024){
        int i=start+tid;
        int gt=0,tie=0;
        if(i<Nn){ unsigned e=fenc(sc[i]); gt=(e>T); tie=(e==T); }
        unsigned ball=__ballot_sync(0xffffffffu,tie!=0);
        int lp=__popc(ball & ((1u<<lane)-1u));
        if(lane==0) wexcl[wid]=__popc(ball);
        __syncthreads();
        if(wid==0){
            int val=wexcl[lane]; int iv=val;
            for(int o=1;o<32;o<<=1){int n=__shfl_up_sync(0xffffffffu,iv,o); if(lane>=o) iv+=n;}
            wexcl[lane]=iv-val;
            if(lane==31) chunktot=iv;
        }
        __syncthreads();
        int pref=running+wexcl[wid]+lp;
        if(i<Nn) g_sel[batch*Nn+i]=(gt||(tie&&pref<R))?1:0;
        __syncthreads();
        if(tid==0) running+=chunktot;
        __syncthreads();
    }
    // deg / gated / touched / prefill / avglog
    float lsum=0.f;
    for(int i=tid;i<Nn;i+=1024){
        int gid=batch*Nn+i;
        int s=g_sel[gid]? g_soutdeg[gid]:0;
        g_outdeg[gid]=s;
        if(layer==0) g_score[gid]=g_c0;
        int dc=s<1?1:s;
        lsum+=logf((float)dc+1.f);
        if(s>0){
            int p=atomicAdd(&g_ngatedB[batch],1);
            g_gatedB[batch*Nn+p]=gid;
            if(g_touched[gid]==0){
                g_touched[gid]=1;
                int q=atomicAdd(&g_ntouched,1);
                g_touchedlist[q]=gid;
            }
        }
    }
    for(int o=16;o>0;o>>=1) lsum+=__shfl_down_sync(0xffffffffu,lsum,o);
    if(lane==0) wlog[wid]=lsum;
    __syncthreads();
    if(wid==0){
        float v=wlog[lane];
        for(int o=16;o>0;o>>=1) v+=__shfl_down_sync(0xffffffffu,v,o);
        if(lane==0) g_avgpart[batch]=v;
    }
}

// u = A·h, v = B·h for all touched nodes; 16 rows/tile, node-pair FFMA2
__global__ void k_tables(const float* __restrict__ preW){
    __shared__ __align__(8) float sh[Dd][18];
    __shared__ int sn[16];
    int tid=threadIdx.x;
    int nt=g_ntouched;
    int ntiles=(nt+15)/16;
    for(int tile=blockIdx.x; tile<ntiles; tile+=gridDim.x){
        int base=tile*16;
        if(tid<16){
            int node=-1;
            if(base+tid<nt) node=g_touchedlist[base+tid];
            sn[tid]=node;
        }
        __syncthreads();
        for(int j=0;j<16;j++){
            int node=sn[j];
            sh[tid][j]=(node>=0)? g_hidden[node*Dd+tid]:0.f;
        }
        __syncthreads();
        ull ua[8], va[8];
        #pragma unroll
        for(int p=0;p<8;p++){ ua[p]=0ull; va[p]=0ull; }
        for(int k=0;k<Dd;k++){
            ull wad=f2dup(preW[k*Dd+tid]);
            ull wbd=f2dup(preW[(Dd+k)*Dd+tid]);
            #pragma unroll
            for(int p=0;p<8;p++){
                ull bv=*reinterpret_cast<const ull*>(&sh[k][2*p]);
                fma2(ua[p],bv,wad); fma2(va[p],bv,wbd);
            }
        }
        #pragma unroll
        for(int p=0;p<8;p++){
            float2 u=f2up(ua[p]), v=f2up(va[p]);
            int na=sn[2*p], nb=sn[2*p+1];
            if(na>=0){ g_utab[na*Dd+tid]=u.x; g_vtab[na*Dd+tid]=v.x; }
            if(nb>=0){ g_utab[nb*Dd+tid]=u.y; g_vtab[nb*Dd+tid]=v.y; }
        }
        __syncthreads();
    }
}

// fused: in-edge aggregation + scalers + post GEMV (f1/f2 factored) + out GEMV + residual
__global__ void k_pna(const float* __restrict__ preb,
                      const float* __restrict__ postW, const float* __restrict__ postb,
                      const float* __restrict__ outW, const float* __restrict__ outb){
    __shared__ __align__(8) float sbase[4*Dd][18];
    __shared__ __align__(8) float stmp[Dd][18];
    __shared__ int snode[16];
    __shared__ float sf1[16], sf2[16];
    int tid=threadIdx.x;
    int n0=g_ngatedB[0], n1=g_ngatedB[1];
    int ng=n0+n1;
    float avg=(g_avgpart[0]+g_avgpart[1])/(float)BNq;
    float pb=preb[tid];
    int ntiles=(ng+15)/16;
    for(int tile=blockIdx.x; tile<ntiles; tile+=gridDim.x){
        int base=tile*16;
        if(tid<16){
            int node=-1;
            int gi=base+tid;
            if(gi<ng) node=(gi<n0)? g_gatedB[gi] : g_gatedB[Nn+gi-n0];
            snode[tid]=node;
            if(node>=0){
                int dg=g_outdeg[node]; if(dg<1) dg=1;
                float logd=logf((float)dg+1.f);
                sf1[tid]=logd/avg; sf2[tid]=avg/logd;
            } else { sf1[tid]=0.f; sf2[tid]=0.f; }
        }
        __syncthreads();
        // aggregation per node (threads parallel over feature dim)
        for(int j=0;j<16;j++){
            int node=snode[j];
            float mean=0.f, mxv=0.f, mnv=0.f, stdv=0.f;
            if(node>=0){
                float u=g_utab[node*Dd+tid];   // gated => touched => valid
                int rs=g_rowptr[node], re=g_rowptr[node+1];
                float s1=0.f,s2=0.f,mx=-INFINITY,mn=INFINITY; int cnt=0;
                for(int e=rs;e<re;e++){
                    int s=g_col[e];
                    if(g_sel[s]){
                        float vv=g_touched[s]? g_vtab[s*Dd+tid]:0.f;
                        float m=pb+u+vv;
                        s1+=m; s2+=m*m;
                        mx=fmaxf(mx,m); mn=fminf(mn,m);
                        cnt++;
                    }
                }
                float denom=(cnt>0)?(float)cnt:1.f;
                mean=s1/denom;
                float var=fmaxf(s2/denom-mean*mean,0.f);
                stdv=sqrtf(var+EPSq);
                mxv=(cnt>0)?mx:0.f; mnv=(cnt>0)?mn:0.f;
            }
            sbase[0*Dd+tid][j]=mean;
            sbase[1*Dd+tid][j]=mxv;
            sbase[2*Dd+tid][j]=mnv;
            sbase[3*Dd+tid][j]=stdv;
        }
        __syncthreads();
        // post GEMV: y = postb + z0 + f1*z1 + f2*z2
        ull z0[8], z1[8], z2[8];
        #pragma unroll
        for(int p=0;p<8;p++){ z0[p]=0ull; z1[p]=0ull; z2[p]=0ull; }
        for(int k=0;k<4*Dd;k++){
            ull w0=f2dup(postW[k*Dd+tid]);
            ull w1=f2dup(postW[(4*Dd+k)*Dd+tid]);
            ull w2=f2dup(postW[(8*Dd+k)*Dd+tid]);
            #pragma unroll
            for(int p=0;p<8;p++){
                ull bv=*reinterpret_cast<const ull*>(&sbase[k][2*p]);
                fma2(z0[p],bv,w0); fma2(z1[p],bv,w1); fma2(z2[p],bv,w2);
            }
        }
        float pob=postb[tid];
        #pragma unroll
        for(int p=0;p<8;p++){
            float2 a=f2up(z0[p]), b=f2up(z1[p]), c=f2up(z2[p]);
            stmp[tid][2*p]   = pob + a.x + sf1[2*p]*b.x   + sf2[2*p]*c.x;
            stmp[tid][2*p+1] = pob + a.y + sf1[2*p+1]*b.y + sf2[2*p+1]*c.y;
        }
        __syncthreads();
        // out GEMV + residual
        ull bb[8];
        #pragma unroll
        for(int p=0;p<8;p++) bb[p]=0ull;
        for(int k=0;k<Dd;k++){
            ull wd=f2dup(outW[k*Dd+tid]);
            #pragma unroll
            for(int p=0;p<8;p++){
                ull bv=*reinterpret_cast<const ull*>(&stmp[k][2*p]);
                fma2(bb[p],bv,wd);
            }
        }
        float ob=outb[tid];
        #pragma unroll
        for(int p=0;p<8;p++){
            float2 r=f2up(bb[p]);
            int na=snode[2*p], nb=snode[2*p+1];
            if(na>=0) g_hidden[na*Dd+tid] += ob + r.x;
            if(nb>=0) g_hidden[nb*Dd+tid] += ob + r.y;
        }
        __syncthreads();
    }
}

// score MLP: layer 0 -> all touched; layers >0 -> this layer's gated only
__global__ void k_score(int layer,
                        const float* __restrict__ linW,
                        const float* __restrict__ m1W, const float* __restrict__ m1b,
                        const float* __restrict__ m2W, const float* __restrict__ m2b){
    __shared__ __align__(8) float sh[Dd][18];
    __shared__ __align__(8) float sx[Dd][18];
    __shared__ __align__(8) float sp[Dd][18];
    __shared__ int sn[16];
    int tid=threadIdx.x;
    int n0g=g_ngatedB[0], n1g=g_ngatedB[1];
    int cnt=(layer==0)? g_ntouched : (n0g+n1g);
    int ntiles=(cnt+15)/16;
    float m2bv=m2b[0];
    for(int tile=blockIdx.x; tile<ntiles; tile+=gridDim.x){
        int base=tile*16;
        if(tid<16){
            int node=-1;
            int gi=base+tid;
            if(gi<cnt){
                if(layer==0) node=g_touchedlist[gi];
                else node=(gi<n0g)? g_gatedB[gi] : g_gatedB[Nn+gi-n0g];
            }
            sn[tid]=node;
        }
        __syncthreads();
        for(int j=0;j<16;j++){
            int node=sn[j];
            sh[tid][j]=(node>=0)? g_hidden[node*Dd+tid]:0.f;
        }
        __syncthreads();
        // a = relc[batch] + h @ linW[:D]
        ull aa[8];
        #pragma unroll
        for(int p=0;p<8;p++) aa[p]=0ull;
        for(int k=0;k<Dd;k++){
            ull wd=f2dup(linW[k*Dd+tid]);
            #pragma unroll
            for(int p=0;p<8;p++){
                ull bv=*reinterpret_cast<const ull*>(&sh[k][2*p]);
                fma2(aa[p],bv,wd);
            }
        }
        #pragma unroll
        for(int p=0;p<8;p++){
            float2 a=f2up(aa[p]);
            int na=sn[2*p], nb=sn[2*p+1];
            float rA=(na>=0)? g_relc[(na/Nn)*Dd+tid]:0.f;
            float rB=(nb>=0)? g_relc[(nb/Nn)*Dd+tid]:0.f;
            sx[tid][2*p]  =(a.x+rA)*sh[tid][2*p];
            sx[tid][2*p+1]=(a.y+rB)*sh[tid][2*p+1];
        }
        __syncthreads();
        // h1 = relu(m1b + x @ m1W); sp = h1 * m2W
        ull hh[8];
        #pragma unroll
        for(int p=0;p<8;p++) hh[p]=0ull;
        for(int k=0;k<Dd;k++){
            ull wd=f2dup(m1W[k*Dd+tid]);
            #pragma unroll
            for(int p=0;p<8;p++){
                ull bv=*reinterpret_cast<const ull*>(&sx[k][2*p]);
                fma2(hh[p],bv,wd);
            }
        }
        float mb=m1b[tid], wm=m2W[tid];
        #pragma unroll
        for(int p=0;p<8;p++){
            float2 h=f2up(hh[p]);
            sp[tid][2*p]  =fmaxf(h.x+mb,0.f)*wm;
            sp[tid][2*p+1]=fmaxf(h.y+mb,0.f)*wm;
        }
        __syncthreads();
        if(tid<16 && sn[tid]>=0){
            float s=0.f;
            for(int k=0;k<Dd;k++) s+=sp[k][tid];
            g_score[sn[tid]]=s+m2bv;
        }
        __syncthreads();
    }
}

__global__ void k_gather(float* out){
    int idx = threadIdx.x;
    if (idx < Bq*NEGq) out[idx] = g_score[g_tgather[idx]];
}

extern "C" void kernel_launch(void* const* d_in, const int* in_sizes, int n_in,
                              void* d_out, int out_size){
    (void)in_sizes; (void)n_in; (void)out_size;
    const int*   h_index = (const int*)  d_in[0];
    const int*   r_index = (const int*)  d_in[1];
    const int*   t_index = (const int*)  d_in[2];
    const float* hs      = (const float*)d_in[3];
    const int*   eidx    = (const int*)  d_in[4];
    const float* rel     = (const float*)d_in[5];
    const float* linW    = (const float*)d_in[6];
    const float* linb    = (const float*)d_in[7];
    const float* m1W     = (const float*)d_in[8];
    const float* m1b     = (const float*)d_in[9];
    const float* m2W     = (const float*)d_in[10];
    const float* m2b     = (const float*)d_in[11];
    const float* preW    = (const float*)d_in[12];
    const float* preb    = (const float*)d_in[13];
    const float* postW   = (const float*)d_in[14];
    const float* postb   = (const float*)d_in[15];
    const float* outW    = (const float*)d_in[16];
    const float* outb    = (const float*)d_in[17];
    float* out = (float*)d_out;

    k_setup<<<1,256>>>(h_index, r_index, t_index, hs, rel, m1b, m2W, m2b);
    k_clear_state<<<2048,256>>>();
    k_csr_count<<<(BEq+255)/256,256>>>(eidx);
    k_scanA<<<NBLK,1024>>>();
    k_scanB<<<1,32>>>();
    k_scanC<<<NBLK,1024>>>();
    k_csr_fill<<<(BEq+255)/256,256>>>(eidx);
    k_boundary<<<Bq,Dd>>>();
    k_init_relc_score<<<Bq,Dd>>>(linW, linb, m1W, m1b, m2W, m2b);

    for (int l=0; l<Lq; l++){
        k_selmark<<<Bq,1024>>>(l);
        k_tables<<<148,Dd>>>(preW + (size_t)l*2*Dd*Dd);
        k_pna<<<148,Dd>>>(preb + (size_t)l*Dd,
                          postW + (size_t)l*12*Dd*Dd, postb + (size_t)l*Dd,
                          outW  + (size_t)l*Dd*Dd,    outb  + (size_t)l*Dd);
        k_score<<<148,Dd>>>(l, linW, m1W, m1b, m2W, m2b);
    }
    k_gather<<<1,32>>>(out);
}

// round 9
// speedup vs baseline: 1.0222x; 1.0222x over previous
#include <cuda_runtime.h>
#include <math.h>

#define Bq 2
#define NEGq 16
#define Nn 10000
#define Ee 80000
#define Dd 128
#define NUMREL 237
#define Lq 3
#define Kq 1000
#define BNq (Bq*Nn)
#define BEq (Bq*Ee)
#define EPSq 1e-5f
#define GRID 148
#define TPB 256
#define SCH 512
#define NB2 ((BNq+SCH-1)/SCH)

typedef unsigned long long ull;

// ----------------- persistent device scratch (no allocations) -----------------
__device__ float g_hidden[BNq*Dd];
__device__ float g_score[BNq];
__device__ unsigned char g_sel[BNq];
__device__ int   g_outdeg[BNq];
__device__ int   g_soutdeg[BNq];
__device__ int   g_indeg[BNq];       // CSR count / fill cursor
__device__ int   g_rowptr[BNq+1];
__device__ int   g_col[BEq];         // CSR-by-dst: src flat ids
__device__ float g_utab[BNq*Dd];     // A·h, node-indexed (valid iff touched)
__device__ float g_vtab[BNq*Dd];     // B·h, node-indexed (valid iff touched)
__device__ int   g_gatedB[Bq*Nn];
__device__ int   g_ngatedB[Bq];
__device__ int   g_touchedlist[BNq];
__device__ unsigned char g_touched[BNq];
__device__ float g_rel[Bq*Dd];
__device__ float g_relc[Bq*Dd];      // linb + rel @ linW[D:2D]
__device__ float g_hvals[Bq*Dd];
__device__ float g_tvals[Bq*Dd];
__device__ int   g_flat_h[Bq];
__device__ int   g_flat_t[Bq];
__device__ int   g_tgather[Bq*NEGq];
__device__ int   g_ntouched;
__device__ int   g_ntfrozen;         // barrier-frozen snapshot of g_ntouched
__device__ float g_avgpart[Bq];
__device__ float g_c0;
__device__ int   g_btot[64];
__device__ int   g_boff[64];
__device__ int   g_barcnt;
__device__ volatile int g_barepoch;

__device__ __forceinline__ unsigned fenc(float f){
    unsigned u = __float_as_uint(f);
    return (u & 0x80000000u) ? ~u : (u | 0x80000000u);
}

// ----- packed f32x2 helpers (sm_103a FFMA2) -----
__device__ __forceinline__ ull f2pk(float lo, float hi){
    ull r; asm("mov.b64 %0, {%1,%2};" : "=l"(r) : "f"(lo), "f"(hi)); return r;
}
__device__ __forceinline__ ull f2dup(float w){ return f2pk(w,w); }
__device__ __forceinline__ void fma2(ull &d, ull a, ull b){
    asm("fma.rn.f32x2 %0, %1, %2, %0;" : "+l"(d) : "l"(a), "l"(b));
}
__device__ __forceinline__ float2 f2up(ull v){
    float lo, hi; asm("mov.b64 {%0,%1}, %2;" : "=f"(lo), "=f"(hi) : "l"(v));
    return make_float2(lo,hi);
}

// reset barrier state every invocation: no launch can inherit dirty state
__global__ void k_barinit(){
    g_barcnt = 0;
    g_barepoch = 0;
    g_ntfrozen = 0;
    __threadfence();
}

// ----------------- the mega kernel -----------------
__global__ void __launch_bounds__(TPB)
k_mega(const int* __restrict__ h_index, const int* __restrict__ r_index,
       const int* __restrict__ t_index, const float* __restrict__ hidden_states,
       const int* __restrict__ edge_index, const float* __restrict__ rel_embedding,
       const float* __restrict__ linW, const float* __restrict__ linb,
       const float* __restrict__ m1W, const float* __restrict__ m1b,
       const float* __restrict__ m2W, const float* __restrict__ m2b,
       const float* __restrict__ preW, const float* __restrict__ preb,
       const float* __restrict__ postW, const float* __restrict__ postb,
       const float* __restrict__ outW, const float* __restrict__ outb,
       float* __restrict__ out)
{
    __shared__ __align__(16) float S[11520];   // 46080 B, aliased per phase
    __shared__ int   I[96];
    __shared__ float F[96];

    const int tid = threadIdx.x;
    const int bid = blockIdx.x;
    const int lane = tid & 31;
    const int w = tid >> 5;
    const int t = tid & 127;
    const int hk = tid >> 7;
    const int gid0 = bid*TPB + tid;
    const int gstride = GRID*TPB;

    int epoch = 0;   // k_barinit guarantees g_barepoch==0 at kernel start

    // grid barrier; releaser also freezes the touched counter
    #define GRIDBAR() do{ \
        __syncthreads(); \
        epoch++; \
        if (tid==0){ \
            __threadfence(); \
            if (atomicAdd(&g_barcnt,1)==GRID-1){ \
                g_barcnt=0; g_ntfrozen=g_ntouched; __threadfence(); g_barepoch=epoch; \
            } else { \
                while (g_barepoch != epoch) __nanosleep(64); \
            } \
        } \
        __syncthreads(); \
        __threadfence(); \
    }while(0)

    // ---------- P0: clear + setup ----------
    {
        float4 z4 = make_float4(0.f,0.f,0.f,0.f);
        for (int i=gid0; i<(BNq*Dd)/4; i+=gstride) ((float4*)g_hidden)[i]=z4;
        for (int i=gid0; i<BNq; i+=gstride){
            g_score[i]=0.f; g_touched[i]=0; g_indeg[i]=0; g_soutdeg[i]=0;
        }
        if (bid==0){
            if (tid < Bq){
                int b = tid;
                int h0 = h_index[b*NEGq];
                int neg = 1;
                for (int j=1;j<NEGq;j++) if (h_index[b*NEGq+j]!=h0) neg=0;
                int hh = neg ? h0 : t_index[b*NEGq];
                int tt = neg ? t_index[b*NEGq] : h0;
                int rr = neg ? r_index[b*NEGq] : r_index[b*NEGq] + NUMREL;
                I[tid]=hh; I[8+tid]=tt; I[16+tid]=rr; I[24+tid]=neg;
                g_flat_h[b] = hh + b*Nn;
                g_flat_t[b] = tt + b*Nn;
            }
            if (tid==0) g_ntouched = 0;
            __syncthreads();
            for (int idx=tid; idx<Bq*NEGq; idx+=TPB){
                int b = idx/NEGq;
                int tv = I[24+b] ? t_index[idx] : h_index[idx];
                g_tgather[idx] = tv + b*Nn;
            }
            for (int idx=tid; idx<Bq*Dd; idx+=TPB){
                int b = idx/Dd; int d = idx - b*Dd;
                g_rel[idx] = rel_embedding[I[16+b]*Dd + d];
                // literal repeat_interleave(N)[:B] quirk -> row 0 for all b
                g_hvals[idx] = hidden_states[I[0]*Dd + d];
                g_tvals[idx] = hidden_states[I[8]*Dd + d];
            }
            // c0 = relu(m1b)@m2W + m2b
            float v = (tid<Dd) ? fmaxf(m1b[tid],0.f)*m2W[tid] : 0.f;
            for (int o=16;o>0;o>>=1) v += __shfl_down_sync(0xffffffffu,v,o);
            if (lane==0) F[w]=v;
            __syncthreads();
            if (tid==0){
                float s=0.f; for(int i=0;i<8;i++) s+=F[i];
                g_c0 = s + m2b[0];
            }
        }
    }
    GRIDBAR();

    // ---------- P1: CSR count ----------
    for (int e=gid0; e<BEq; e+=gstride){
        int b = e/Ee, ei = e - b*Ee;
        atomicAdd(&g_indeg[edge_index[Ee+ei] + b*Nn], 1);
        atomicAdd(&g_soutdeg[edge_index[ei] + b*Nn], 1);
    }
    GRIDBAR();

    // ---------- P2: per-block local scan (512 entries/block) ----------
    if (bid < NB2){
        int base = bid*SCH;
        int i0 = base + 2*tid, i1 = i0+1;
        int c0 = (i0<BNq)? g_indeg[i0]:0;
        int c1 = (i1<BNq)? g_indeg[i1]:0;
        int s = c0+c1, inc = s;
        for (int o=1;o<32;o<<=1){ int n=__shfl_up_sync(0xffffffffu,inc,o); if(lane>=o) inc+=n; }
        if (lane==31) I[w]=inc;
        __syncthreads();
        if (tid<8){
            int v=I[tid], iv=v;
            for (int o=1;o<8;o<<=1){ int n=__shfl_up_sync(0xffu,iv,o); if(tid>=o) iv+=n; }
            I[8+tid]=iv-v;
            if (tid==7) g_btot[bid]=iv;
        }
        __syncthreads();
        int excl = I[8+w] + inc - s;
        if (i0<BNq) g_rowptr[i0]=excl;
        if (i1<BNq) g_rowptr[i1]=excl+c0;
    }
    GRIDBAR();

    // ---------- P3: block totals scan ----------
    if (bid==0 && tid<NB2){
        int s=0;
        for (int i=0;i<tid;i++) s += g_btot[i];
        g_boff[tid]=s;
    }
    GRIDBAR();

    // ---------- P4: add offsets, set fill cursor ----------
    for (int i=gid0; i<BNq; i+=gstride){
        int r = g_rowptr[i] + g_boff[i/SCH];
        g_rowptr[i]=r; g_indeg[i]=r;
    }
    if (gid0==0) g_rowptr[BNq]=BEq;
    GRIDBAR();

    // ---------- P5: CSR fill ----------
    for (int e=gid0; e<BEq; e+=gstride){
        int b = e/Ee, ei = e - b*Ee;
        int s = edge_index[ei] + b*Nn;
        int d = edge_index[Ee+ei] + b*Nn;
        int pos = atomicAdd(&g_indeg[d],1);
        g_col[pos]=s;
    }
    GRIDBAR();

    // ---------- P6: boundary + relc + head init score (blocks 0,1) ----------
    if (bid < Bq){
        int b = bid;
        int fh = g_flat_h[b], ft = g_flat_t[b];
        if (tid<Dd){
            if (ft!=fh) g_hidden[ft*Dd+tid]=g_tvals[b*Dd+tid];
            g_hidden[fh*Dd+tid]=g_hvals[b*Dd+tid];
        }
        if (tid==0){
            int p=atomicAdd(&g_ntouched,1); g_touchedlist[p]=fh; g_touched[fh]=1;
            if (ft!=fh){ p=atomicAdd(&g_ntouched,1); g_touchedlist[p]=ft; g_touched[ft]=1; }
        }
        float *shv=S, *srl=S+128, *sxv=S+256, *spv=S+384;
        if (tid<Dd){ shv[tid]=g_hvals[b*Dd+tid]; srl[tid]=g_rel[b*Dd+tid]; }
        __syncthreads();
        if (tid<Dd){
            float rc=linb[tid];
            for (int k=0;k<Dd;k++) rc += srl[k]*linW[(Dd+k)*Dd+tid];
            g_relc[b*Dd+tid]=rc;
            float acc=rc;
            for (int k=0;k<Dd;k++) acc += shv[k]*linW[k*Dd+tid];
            sxv[tid]=acc*shv[tid];
        }
        __syncthreads();
        if (tid<Dd){
            float h=m1b[tid];
            for (int k=0;k<Dd;k++) h += sxv[k]*m1W[k*Dd+tid];
            spv[tid]=fmaxf(h,0.f)*m2W[tid];
        }
        __syncthreads();
        if (tid==0){
            float s=0.f; for (int k=0;k<Dd;k++) s+=spv[k];
            g_score[fh]=s+m2b[0];
        }
    }
    GRIDBAR();

    // =================== layer loop ===================
    for (int l=0; l<Lq; l++){
        const float* preWl  = preW  + (size_t)l*2*Dd*Dd;
        const float* prebl  = preb  + (size_t)l*Dd;
        const float* postWl = postW + (size_t)l*12*Dd*Dd;
        const float* postbl = postb + (size_t)l*Dd;
        const float* outWl  = outW  + (size_t)l*Dd*Dd;
        const float* outbl  = outb  + (size_t)l*Dd;

        int nt_old = g_ntfrozen;   // barrier-frozen snapshot: stable, race-free

        // ---------- P7: selmark (blocks 0,1)  ||  tables over frozen touched (blocks 2+) ----------
        if (bid < Bq){
            int batch = bid;
            unsigned* hist=(unsigned*)S;
            unsigned* ts  =(unsigned*)S+4096;
            unsigned* ws  =(unsigned*)S+4352;
            const float* sc = g_score + batch*Nn;
            if (tid==0){ I[88]=0; I[89]=0; I[90]=0; g_ngatedB[batch]=0; }
            __syncthreads();
            for (int lvl=0;lvl<3;lvl++){
                for (int i=tid;i<4096;i+=TPB) hist[i]=0u;
                __syncthreads();
                unsigned p=(unsigned)I[88];
                for (int i=tid;i<Nn;i+=TPB){
                    unsigned e=fenc(sc[i]); unsigned key; bool ok;
                    if (lvl==0){ ok=true;            key=e>>20; }
                    else if (lvl==1){ ok=((e>>20)==p); key=(e>>8)&0xFFFu; }
                    else            { ok=((e>>8)==p);  key=e&0xFFu; }
                    if (ok) atomicAdd(&hist[key],1u);
                }
                __syncthreads();
                unsigned tsum=0u;
                #pragma unroll
                for (int i=0;i<16;i++) tsum += hist[tid*16+i];
                ts[tid]=tsum;
                unsigned wv=tsum;
                for (int o=16;o>0;o>>=1) wv+=__shfl_down_sync(0xffffffffu,wv,o);
                if (lane==0) ws[w]=wv;
                __syncthreads();
                if (tid==0){
                    unsigned R=(unsigned)Kq-(unsigned)I[89];
                    unsigned acc=0u; int beta=0, wsel=0, tsel=0;
                    for (int ww=7;ww>=0;ww--){
                        if (acc+ws[ww]>=R){ wsel=ww; break; }
                        acc+=ws[ww];
                    }
                    for (int tt=wsel*32+31;tt>=wsel*32;tt--){
                        if (acc+ts[tt]>=R){ tsel=tt; break; }
                        acc+=ts[tt];
                    }
                    for (int b2=tsel*16+15;b2>=tsel*16;b2--){
                        if (acc+hist[b2]>=R){ beta=b2; break; }
                        acc+=hist[b2];
                    }
                    I[89]=(int)((unsigned)I[89]+acc);
                    unsigned sp=(unsigned)I[88];
                    I[88]=(int)((lvl==0)?(unsigned)beta:((sp<<((lvl==1)?12:8))|(unsigned)beta));
                }
                __syncthreads();
            }
            unsigned T=(unsigned)I[88]; int R=Kq-I[89];
            for (int start=0;start<Nn;start+=TPB){
                int i=start+tid;
                int gt=0,tie=0;
                if (i<Nn){ unsigned e=fenc(sc[i]); gt=(e>T); tie=(e==T); }
                unsigned ball=__ballot_sync(0xffffffffu,tie!=0);
                int lp=__popc(ball&((1u<<lane)-1u));
                if (lane==0) I[64+w]=__popc(ball);
                __syncthreads();
                if (tid<8){
                    int v=I[64+tid], iv=v;
                    for (int o=1;o<8;o<<=1){ int n=__shfl_up_sync(0xffu,iv,o); if(tid>=o) iv+=n; }
                    I[72+tid]=iv-v;
                    if (tid==7) I[91]=iv;
                }
                __syncthreads();
                int pref=I[90]+I[72+w]+lp;
                if (i<Nn) g_sel[batch*Nn+i]=(gt||(tie&&pref<R))?1:0;
                __syncthreads();
                if (tid==0) I[90]+=I[91];
                __syncthreads();
            }
            float lsum=0.f;
            for (int i=tid;i<Nn;i+=TPB){
                int g=batch*Nn+i;
                int s=g_sel[g]? g_soutdeg[g]:0;
                g_outdeg[g]=s;
                if (l==0) g_score[g]=g_c0;
                int dc=s<1?1:s;
                lsum+=logf((float)dc+1.f);
                if (s>0){
                    int p=atomicAdd(&g_ngatedB[batch],1);
                    g_gatedB[batch*Nn+p]=g;
                    if (g_touched[g]==0){
                        g_touched[g]=1;
                        int q=atomicAdd(&g_ntouched,1);
                        g_touchedlist[q]=g;
                    }
                }
            }
            for (int o=16;o>0;o>>=1) lsum+=__shfl_down_sync(0xffffffffu,lsum,o);
            if (lane==0) F[w]=lsum;
            __syncthreads();
            if (tid==0){
                float v=0.f; for (int i=0;i<8;i++) v+=F[i];
                g_avgpart[batch]=v;
            }
        } else {
            // tables over [0, nt_old) — frozen list region, race-free
            float (*sh)[18]=(float(*)[18])S;
            int ntiles=(nt_old+15)/16;
            for (int tile=bid-Bq; tile<ntiles; tile+=GRID-Bq){
                int base=tile*16;
                if (tid<16) I[tid]=(base+tid<nt_old)? g_touchedlist[base+tid]:-1;
                __syncthreads();
                for (int jj=0;jj<8;jj++){
                    int j=hk*8+jj, node=I[j];
                    sh[t][j]=(node>=0)? g_hidden[node*Dd+t]:0.f;
                }
                __syncthreads();
                ull acc[8];
                #pragma unroll
                for (int p=0;p<8;p++) acc[p]=0ull;
                const float* wcol = preWl + (size_t)hk*Dd*Dd;
                for (int k=0;k<Dd;k++){
                    ull wd=f2dup(wcol[k*Dd+t]);
                    #pragma unroll
                    for (int p=0;p<8;p++){
                        ull bv=*(const ull*)&sh[k][2*p];
                        fma2(acc[p],bv,wd);
                    }
                }
                float* dst = hk? g_vtab : g_utab;
                #pragma unroll
                for (int p=0;p<8;p++){
                    float2 r=f2up(acc[p]);
                    int na=I[2*p], nb=I[2*p+1];
                    if (na>=0) dst[na*Dd+t]=r.x;
                    if (nb>=0) dst[nb*Dd+t]=r.y;
                }
                __syncthreads();
            }
        }
        GRIDBAR();

        // ---------- P8: tables over [nt_old, nt_new) (all blocks) ----------
        {
            int nt_new = g_ntfrozen;   // frozen at P7's barrier
            int cnt = nt_new - nt_old;
            float (*sh)[18]=(float(*)[18])S;
            int ntiles=(cnt+15)/16;
            for (int tile=bid; tile<ntiles; tile+=GRID){
                int base=nt_old+tile*16;
                if (tid<16) I[tid]=(base+tid<nt_new)? g_touchedlist[base+tid]:-1;
                __syncthreads();
                for (int jj=0;jj<8;jj++){
                    int j=hk*8+jj, node=I[j];
                    sh[t][j]=(node>=0)? g_hidden[node*Dd+t]:0.f;
                }
                __syncthreads();
                ull acc[8];
                #pragma unroll
                for (int p=0;p<8;p++) acc[p]=0ull;
                const float* wcol = preWl + (size_t)hk*Dd*Dd;
                for (int k=0;k<Dd;k++){
                    ull wd=f2dup(wcol[k*Dd+t]);
                    #pragma unroll
                    for (int p=0;p<8;p++){
                        ull bv=*(const ull*)&sh[k][2*p];
                        fma2(acc[p],bv,wd);
                    }
                }
                float* dst = hk? g_vtab : g_utab;
                #pragma unroll
                for (int p=0;p<8;p++){
                    float2 r=f2up(acc[p]);
                    int na=I[2*p], nb=I[2*p+1];
                    if (na>=0) dst[na*Dd+t]=r.x;
                    if (nb>=0) dst[nb*Dd+t]=r.y;
                }
                __syncthreads();
            }
        }
        GRIDBAR();

        // ---------- P9: pna (aggregate + post/out GEMV + residual) ----------
        {
            float (*sbase)[18]=(float(*)[18])S;             // 512 rows
            float (*stmp)[18] =(float(*)[18])(S+512*18);    // 128 rows
            int n0=g_ngatedB[0], n1=g_ngatedB[1];
            int ng=n0+n1;
            float avg=(g_avgpart[0]+g_avgpart[1])/(float)BNq;
            float pb=prebl[t];
            int ntiles=(ng+15)/16;
            for (int tile=bid; tile<ntiles; tile+=GRID){
                int base=tile*16;
                if (tid<16){
                    int gi=base+tid, node=-1;
                    if (gi<ng) node=(gi<n0)? g_gatedB[gi] : g_gatedB[Nn+gi-n0];
                    I[tid]=node;
                    if (node>=0){
                        int dg=g_outdeg[node];
                        float logd=logf((float)(dg<1?1:dg)+1.f);
                        F[tid]=logd/avg; F[16+tid]=avg/logd;
                    } else { F[tid]=0.f; F[16+tid]=0.f; }
                }
                __syncthreads();
                for (int jj=0;jj<8;jj++){
                    int j=hk*8+jj, node=I[j];
                    float mean=0.f,mxv=0.f,mnv=0.f,stdv=0.f;
                    if (node>=0){
                        float u=g_utab[node*Dd+t];
                        int rs=g_rowptr[node], re=g_rowptr[node+1];
                        float s1=0.f,s2=0.f,mx=-INFINITY,mn=INFINITY; int cnt=0;
                        for (int e=rs;e<re;e++){
                            int s=g_col[e];
                            if (g_sel[s]){
                                float vv=g_touched[s]? g_vtab[s*Dd+t]:0.f;
                                float m=pb+u+vv;
                                s1+=m; s2+=m*m; mx=fmaxf(mx,m); mn=fminf(mn,m); cnt++;
                            }
                        }
                        float denom=(cnt>0)?(float)cnt:1.f;
                        mean=s1/denom;
                        float var=fmaxf(s2/denom-mean*mean,0.f);
                        stdv=sqrtf(var+EPSq);
                        mxv=(cnt>0)?mx:0.f; mnv=(cnt>0)?mn:0.f;
                    }
                    sbase[0*Dd+t][j]=mean; sbase[1*Dd+t][j]=mxv;
                    sbase[2*Dd+t][j]=mnv;  sbase[3*Dd+t][j]=stdv;
                }
                __syncthreads();
                ull z0[4],z1[4],z2[4];
                #pragma unroll
                for (int p=0;p<4;p++){ z0[p]=0ull; z1[p]=0ull; z2[p]=0ull; }
                for (int k=0;k<4*Dd;k++){
                    ull w0=f2dup(postWl[k*Dd+t]);
                    ull w1=f2dup(postWl[(4*Dd+k)*Dd+t]);
                    ull w2=f2dup(postWl[(8*Dd+k)*Dd+t]);
                    #pragma unroll
                    for (int p=0;p<4;p++){
                        int pp=hk*4+p;
                        ull bv=*(const ull*)&sbase[k][2*pp];
                        fma2(z0[p],bv,w0); fma2(z1[p],bv,w1); fma2(z2[p],bv,w2);
                    }
                }
                float pob=postbl[t];
                #pragma unroll
                for (int p=0;p<4;p++){
                    int pp=hk*4+p;
                    float2 a=f2up(z0[p]), b=f2up(z1[p]), c=f2up(z2[p]);
                    stmp[t][2*pp]  =pob+a.x+F[2*pp]*b.x  +F[16+2*pp]*c.x;
                    stmp[t][2*pp+1]=pob+a.y+F[2*pp+1]*b.y+F[16+2*pp+1]*c.y;
                }
                __syncthreads();
                ull bb[4];
                #pragma unroll
                for (int p=0;p<4;p++) bb[p]=0ull;
                for (int k=0;k<Dd;k++){
                    ull wd=f2dup(outWl[k*Dd+t]);
                    #pragma unroll
                    for (int p=0;p<4;p++){
                        int pp=hk*4+p;
                        ull bv=*(const ull*)&stmp[k][2*pp];
                        fma2(bb[p],bv,wd);
                    }
                }
                float ob=outbl[t];
                #pragma unroll
                for (int p=0;p<4;p++){
                    int pp=hk*4+p;
                    float2 r=f2up(bb[p]);
                    int na=I[2*pp], nb=I[2*pp+1];
                    if (na>=0) g_hidden[na*Dd+t]+=ob+r.x;
                    if (nb>=0) g_hidden[nb*Dd+t]+=ob+r.y;
                }
                __syncthreads();
            }
        }
        GRIDBAR();

        // ---------- P10: score (layer 0: all touched; else this layer's gated) ----------
        {
            float (*sh)[18]=(float(*)[18])S;
            float (*sx)[18]=(float(*)[18])(S+2304);
            float (*sp)[18]=(float(*)[18])(S+4608);
            float* part=S+6912;   // 256 floats
            int n0=g_ngatedB[0], n1=g_ngatedB[1];
            int cnt=(l==0)? g_ntfrozen : (n0+n1);
            float m2bv=m2b[0];
            int ntiles=(cnt+15)/16;
            for (int tile=bid; tile<ntiles; tile+=GRID){
                int base=tile*16;
                if (tid<16){
                    int gi=base+tid, node=-1;
                    if (gi<cnt){
                        if (l==0) node=g_touchedlist[gi];
                        else node=(gi<n0)? g_gatedB[gi] : g_gatedB[Nn+gi-n0];
                    }
                    I[tid]=node;
                }
                __syncthreads();
                for (int jj=0;jj<8;jj++){
                    int j=hk*8+jj, node=I[j];
                    sh[t][j]=(node>=0)? g_hidden[node*Dd+t]:0.f;
                }
                __syncthreads();
                ull aa[4];
                #pragma unroll
                for (int p=0;p<4;p++) aa[p]=0ull;
                for (int k=0;k<Dd;k++){
                    ull wd=f2dup(linW[k*Dd+t]);
                    #pragma unroll
                    for (int p=0;p<4;p++){
                        int pp=hk*4+p;
                        ull bv=*(const ull*)&sh[k][2*pp];
                        fma2(aa[p],bv,wd);
                    }
                }
                #pragma unroll
                for (int p=0;p<4;p++){
                    int pp=hk*4+p;
                    float2 a=f2up(aa[p]);
                    int na=I[2*pp], nb=I[2*pp+1];
                    float rA=(na>=0)? g_relc[(na/Nn)*Dd+t]:0.f;
                    float rB=(nb>=0)? g_relc[(nb/Nn)*Dd+t]:0.f;
                    sx[t][2*pp]  =(a.x+rA)*sh[t][2*pp];
                    sx[t][2*pp+1]=(a.y+rB)*sh[t][2*pp+1];
                }
                __syncthreads();
                ull hh[4];
                #pragma unroll
                for (int p=0;p<4;p++) hh[p]=0ull;
                for (int k=0;k<Dd;k++){
                    ull wd=f2dup(m1W[k*Dd+t]);
                    #pragma unroll
                    for (int p=0;p<4;p++){
                        int pp=hk*4+p;
                        ull bv=*(const ull*)&sx[k][2*pp];
                        fma2(hh[p],bv,wd);
                    }
                }
                float mb=m1b[t], wm=m2W[t];
                #pragma unroll
                for (int p=0;p<4;p++){
                    int pp=hk*4+p;
                    float2 h=f2up(hh[p]);
                    sp[t][2*pp]  =fmaxf(h.x+mb,0.f)*wm;
                    sp[t][2*pp+1]=fmaxf(h.y+mb,0.f)*wm;
                }
                __syncthreads();
                {
                    int j=tid>>4, kg=tid&15;
                    float s=0.f;
                    for (int k=kg*8;k<kg*8+8;k++) s+=sp[k][j];
                    part[tid]=s;
                }
                __syncthreads();
                if (tid<16 && I[tid]>=0){
                    float s=0.f;
                    for (int kg=0;kg<16;kg++) s+=part[tid*16+kg];
                    g_score[I[tid]]=s+m2bv;
                }
                __syncthreads();
            }
        }
        GRIDBAR();
    }

    // ---------- final gather ----------
    if (bid==0 && tid<Bq*NEGq)
        out[tid] = g_score[g_tgather[tid]];

    #undef GRIDBAR
}

extern "C" void kernel_launch(void* const* d_in, const int* in_sizes, int n_in,
                              void* d_out, int out_size){
    (void)in_sizes; (void)n_in; (void)out_size;
    k_barinit<<<1,1>>>();
    k_mega<<<GRID, TPB>>>(
        (const int*)d_in[0], (const int*)d_in[1], (const int*)d_in[2],
        (const float*)d_in[3], (const int*)d_in[4], (const float*)d_in[5],
        (const float*)d_in[6], (const float*)d_in[7],
        (const float*)d_in[8], (const float*)d_in[9],
        (const float*)d_in[10], (const float*)d_in[11],
        (const float*)d_in[12], (const float*)d_in[13],
        (const float*)d_in[14], (const float*)d_in[15],
        (const float*)d_in[16], (const float*)d_in[17],
        (float*)d_out);
}

// round 12
// speedup vs baseline: 1.3140x; 1.2855x over previous
#include <cuda_runtime.h>
#include <math.h>

#define Bq 2
#define NEGq 16
#define Nn 10000
#define Ee 80000
#define Dd 128
#define NUMREL 237
#define Lq 3
#define Kq 1000
#define BNq (Bq*Nn)
#define BEq (Bq*Ee)
#define EPSq 1e-5f
#define GRID 148
#define TPB 512
#define SCH 512
#define NB2 ((BNq+SCH-1)/SCH)

typedef unsigned long long ull;

__device__ float g_hidden[BNq*Dd];
__device__ float g_score[BNq];
__device__ unsigned char g_sel[BNq];
__device__ int   g_outdeg[BNq];
__device__ int   g_soutdeg[BNq];
__device__ int   g_indeg[BNq];
__device__ int   g_rowptr[BNq+1];
__device__ int   g_col[BEq];
__device__ float g_utab[BNq*Dd];
__device__ float g_vtab[BNq*Dd];
__device__ int   g_gatedB[Bq*Nn];
__device__ int   g_ngatedB[Bq];
__device__ int   g_touchedlist[BNq];
__device__ unsigned char g_touched[BNq];
__device__ float g_rel[Bq*Dd];
__device__ float g_relc[Bq*Dd];
__device__ float g_hvals[Bq*Dd];
__device__ float g_tvals[Bq*Dd];
__device__ int   g_flat_h[Bq];
__device__ int   g_flat_t[Bq];
__device__ int   g_tgather[Bq*NEGq];
__device__ int   g_ntouched;
__device__ int   g_ntfrozen;
__device__ float g_avgpart[Bq];
__device__ float g_c0;
__device__ int   g_btot[64];
__device__ int   g_barcnt;
__device__ volatile int g_barepoch;

__device__ __forceinline__ unsigned fenc(float f){
    unsigned u = __float_as_uint(f);
    return (u & 0x80000000u) ? ~u : (u | 0x80000000u);
}
__device__ __forceinline__ ull f2pk(float lo, float hi){
    ull r; asm("mov.b64 %0, {%1,%2};" : "=l"(r) : "f"(lo), "f"(hi)); return r;
}
__device__ __forceinline__ ull f2dup(float w){ return f2pk(w,w); }
__device__ __forceinline__ void fma2(ull &d, ull a, ull b){
    asm("fma.rn.f32x2 %0, %1, %2, %0;" : "+l"(d) : "l"(a), "l"(b));
}
__device__ __forceinline__ float2 f2up(ull v){
    float lo, hi; asm("mov.b64 {%0,%1}, %2;" : "=f"(lo), "=f"(hi) : "l"(v));
    return make_float2(lo,hi);
}

__global__ void k_barinit(){
    g_barcnt = 0; g_barepoch = 0; g_ntfrozen = 0;
    __threadfence();
}

__global__ void __launch_bounds__(TPB)
k_mega(const int* __restrict__ h_index, const int* __restrict__ r_index,
       const int* __restrict__ t_index, const float* __restrict__ hidden_states,
       const int* __restrict__ edge_index, const float* __restrict__ rel_embedding,
       const float* __restrict__ linW, const float* __restrict__ linb,
       const float* __restrict__ m1W, const float* __restrict__ m1b,
       const float* __restrict__ m2W, const float* __restrict__ m2b,
       const float* __restrict__ preW, const float* __restrict__ preb,
       const float* __restrict__ postW, const float* __restrict__ postb,
       const float* __restrict__ outW, const float* __restrict__ outb,
       float* __restrict__ out)
{
    __shared__ __align__(16) float S[11520];
    __shared__ int   I[96];
    __shared__ float F[96];

    const int tid=threadIdx.x, bid=blockIdx.x;
    const int lane=tid&31, w=tid>>5;         // 16 warps
    const int lt=tid&127, hk=tid>>7;         // 4 groups of 128
    const int gid0=bid*TPB+tid, gstride=GRID*TPB;
    int epoch=0;

    #define GRIDBAR() do{ \
        __syncthreads(); \
        epoch++; \
        if (tid==0){ \
            __threadfence(); \
            if (atomicAdd(&g_barcnt,1)==GRID-1){ \
                g_barcnt=0; g_ntfrozen=g_ntouched; __threadfence(); g_barepoch=epoch; \
            } else { while (g_barepoch != epoch) __nanosleep(64); } \
            __threadfence(); \
        } \
        __syncthreads(); \
    }while(0)

    // ---------- P0: clear + setup ----------
    {
        float4 z4 = make_float4(0.f,0.f,0.f,0.f);
        for (int i=gid0; i<(BNq*Dd)/4; i+=gstride) ((float4*)g_hidden)[i]=z4;
        for (int i=gid0; i<BNq; i+=gstride){
            g_score[i]=0.f; g_touched[i]=0; g_indeg[i]=0; g_soutdeg[i]=0;
        }
        if (bid==0){
            if (tid < Bq){
                int b = tid;
                int h0 = h_index[b*NEGq];
                int neg = 1;
                for (int j=1;j<NEGq;j++) if (h_index[b*NEGq+j]!=h0) neg=0;
                int hh = neg ? h0 : t_index[b*NEGq];
                int tt = neg ? t_index[b*NEGq] : h0;
                int rr = neg ? r_index[b*NEGq] : r_index[b*NEGq] + NUMREL;
                I[tid]=hh; I[8+tid]=tt; I[16+tid]=rr; I[24+tid]=neg;
                g_flat_h[b] = hh + b*Nn;
                g_flat_t[b] = tt + b*Nn;
            }
            if (tid==0) g_ntouched = 0;
            __syncthreads();
            for (int idx=tid; idx<Bq*NEGq; idx+=TPB){
                int b = idx/NEGq;
                int tv = I[24+b] ? t_index[idx] : h_index[idx];
                g_tgather[idx] = tv + b*Nn;
            }
            for (int idx=tid; idx<Bq*Dd; idx+=TPB){
                int b = idx/Dd; int d = idx - b*Dd;
                g_rel[idx] = rel_embedding[I[16+b]*Dd + d];
                g_hvals[idx] = hidden_states[I[0]*Dd + d];   // repeat_interleave quirk -> row 0
                g_tvals[idx] = hidden_states[I[8]*Dd + d];
            }
            float v = (tid<Dd) ? fmaxf(m1b[tid],0.f)*m2W[tid] : 0.f;
            for (int o=16;o>0;o>>=1) v += __shfl_down_sync(0xffffffffu,v,o);
            if (lane==0) F[w]=v;
            __syncthreads();
            if (tid==0){
                float s=0.f; for(int i=0;i<16;i++) s+=F[i];
                g_c0 = s + m2b[0];
            }
        }
    }
    GRIDBAR();

    // ---------- P1: CSR count ----------
    for (int e=gid0; e<BEq; e+=gstride){
        int b = e/Ee, ei = e - b*Ee;
        atomicAdd(&g_indeg[edge_index[Ee+ei] + b*Nn], 1);
        atomicAdd(&g_soutdeg[edge_index[ei] + b*Nn], 1);
    }
    GRIDBAR();

    // ---------- P2: per-block local scan (512/block) ----------
    if (bid < NB2){
        int i = bid*SCH + tid;
        int c = (i<BNq)? g_indeg[i]:0;
        int inc = c;
        for (int o=1;o<32;o<<=1){ int n=__shfl_up_sync(0xffffffffu,inc,o); if(lane>=o) inc+=n; }
        if (lane==31) I[w]=inc;
        __syncthreads();
        if (tid<16){
            int v=I[tid], iv=v;
            for (int o=1;o<16;o<<=1){ int n=__shfl_up_sync(0xffffu,iv,o); if(tid>=o) iv+=n; }
            I[16+tid]=iv-v;
            if (tid==15) g_btot[bid]=iv;
        }
        __syncthreads();
        int excl = I[16+w] + inc - c;
        if (i<BNq) g_rowptr[i]=excl;
    }
    GRIDBAR();

    // ---------- P4: offsets (inline btot scan) + fill cursor ----------
    {
        int* Bo=(int*)S;
        if (tid<NB2){ int s=0; for (int i=0;i<tid;i++) s+=g_btot[i]; Bo[tid]=s; }
        __syncthreads();
        for (int i=gid0; i<BNq; i+=gstride){
            int r = g_rowptr[i] + Bo[i/SCH];
            g_rowptr[i]=r; g_indeg[i]=r;
        }
        if (gid0==0) g_rowptr[BNq]=BEq;
    }
    GRIDBAR();

    // ---------- P5 (bid>=2): CSR fill  ||  P6 (bid 0,1): boundary+relc+init ----------
    if (bid >= 2){
        for (int e=(bid-2)*TPB+tid; e<BEq; e+=(GRID-2)*TPB){
            int b = e/Ee, ei = e - b*Ee;
            int s = edge_index[ei] + b*Nn;
            int d = edge_index[Ee+ei] + b*Nn;
            int pos = atomicAdd(&g_indeg[d],1);
            g_col[pos]=s;
        }
    } else {
        int b = bid;
        int fh = g_flat_h[b], ft = g_flat_t[b];
        if (tid<Dd){
            if (ft!=fh) g_hidden[ft*Dd+tid]=g_tvals[b*Dd+tid];
            g_hidden[fh*Dd+tid]=g_hvals[b*Dd+tid];
        }
        if (tid==0){
            int p=atomicAdd(&g_ntouched,1); g_touchedlist[p]=fh; g_touched[fh]=1;
            if (ft!=fh){ p=atomicAdd(&g_ntouched,1); g_touchedlist[p]=ft; g_touched[ft]=1; }
        }
        float *shv=S, *srl=S+128, *sxv=S+256, *spv=S+384;
        if (tid<Dd){ shv[tid]=g_hvals[b*Dd+tid]; srl[tid]=g_rel[b*Dd+tid]; }
        __syncthreads();
        if (tid<Dd){
            float rc=linb[tid];
            #pragma unroll 4
            for (int k=0;k<Dd;k++) rc += srl[k]*linW[(Dd+k)*Dd+tid];
            g_relc[b*Dd+tid]=rc;
            float acc=rc;
            #pragma unroll 4
            for (int k=0;k<Dd;k++) acc += shv[k]*linW[k*Dd+tid];
            sxv[tid]=acc*shv[tid];
        }
        __syncthreads();
        if (tid<Dd){
            float h=m1b[tid];
            #pragma unroll 4
            for (int k=0;k<Dd;k++) h += sxv[k]*m1W[k*Dd+tid];
            spv[tid]=fmaxf(h,0.f)*m2W[tid];
        }
        __syncthreads();
        if (tid==0){
            float s=0.f; for (int k=0;k<Dd;k++) s+=spv[k];
            g_score[fh]=s+m2b[0];
        }
    }
    GRIDBAR();

    // =================== layer loop ===================
    for (int l=0; l<Lq; l++){
        const float* preWl  = preW  + (size_t)l*2*Dd*Dd;
        const float* prebl  = preb  + (size_t)l*Dd;
        const float* postWl = postW + (size_t)l*12*Dd*Dd;
        const float* postbl = postb + (size_t)l*Dd;
        const float* outWl  = outW  + (size_t)l*Dd*Dd;
        const float* outbl  = outb  + (size_t)l*Dd;

        int nt_old = g_ntfrozen;

        // ---------- P7: selmark (bid 0,1) || tables [0,nt_old) (bid 2+) ----------
        if (bid < Bq){
            int batch = bid;
            unsigned* hist=(unsigned*)S;          // 4096
            unsigned* ts  =(unsigned*)S+4096;     // 512
            const float* sc = g_score + batch*Nn;
            if (tid==0){ I[88]=0; I[89]=0; g_ngatedB[batch]=0; }
            __syncthreads();
            for (int lvl=0;lvl<3;lvl++){
                for (int i=tid;i<4096;i+=TPB) hist[i]=0u;
                __syncthreads();
                unsigned p=(unsigned)I[88];
                const float4* sc4=(const float4*)sc;
                for (int i4=tid;i4<Nn/4;i4+=TPB){
                    float4 v4=sc4[i4];
                    float vv[4]={v4.x,v4.y,v4.z,v4.w};
                    #pragma unroll
                    for (int q=0;q<4;q++){
                        unsigned e=fenc(vv[q]); unsigned key; bool ok;
                        if (lvl==0){ ok=true;            key=e>>20; }
                        else if (lvl==1){ ok=((e>>20)==p); key=(e>>8)&0xFFFu; }
                        else            { ok=((e>>8)==p);  key=e&0xFFu; }
                        if (ok) atomicAdd(&hist[key],1u);
                    }
                }
                __syncthreads();
                unsigned tsum=0u;
                #pragma unroll
                for (int i=0;i<8;i++) tsum += hist[tid*8+i];
                ts[tid]=tsum;
                unsigned wv=tsum;
                for (int o=16;o>0;o>>=1) wv+=__shfl_down_sync(0xffffffffu,wv,o);
                if (lane==0) I[64+w]=(int)wv;
                __syncthreads();
                if (tid==0){
                    unsigned R=(unsigned)Kq-(unsigned)I[89];
                    unsigned acc=0u; int beta=0, wsel=0, tsel=0;
                    for (int ww=15;ww>=0;ww--){
                        if (acc+(unsigned)I[64+ww]>=R){ wsel=ww; break; }
                        acc+=(unsigned)I[64+ww];
                    }
                    for (int tt=wsel*32+31;tt>=wsel*32;tt--){
                        if (acc+ts[tt]>=R){ tsel=tt; break; }
                        acc+=ts[tt];
                    }
                    for (int b2=tsel*8+7;b2>=tsel*8;b2--){
                        if (acc+hist[b2]>=R){ beta=b2; break; }
                        acc+=hist[b2];
                    }
                    I[89]=(int)((unsigned)I[89]+acc);
                    unsigned sp=(unsigned)I[88];
                    I[88]=(int)((lvl==0)?(unsigned)beta:((sp<<((lvl==1)?12:8))|(unsigned)beta));
                }
                __syncthreads();
            }
            unsigned T=(unsigned)I[88]; int R=Kq-I[89];
            // two-pass contiguous mark (exact jax tie order: ascending index)
            {
                const int CH=(Nn+TPB-1)/TPB;
                int lo=tid*CH; if (lo>Nn) lo=Nn;
                int hi=lo+CH;  if (hi>Nn) hi=Nn;
                int c=0;
                for (int i=lo;i<hi;i++) c += (fenc(sc[i])==T);
                int v=c;
                for (int o=1;o<32;o<<=1){ int n=__shfl_up_sync(0xffffffffu,v,o); if(lane>=o) v+=n; }
                if (lane==31) I[w]=v;
                __syncthreads();
                if (tid<16){
                    int x=I[tid], ix=x;
                    for (int o=1;o<16;o<<=1){ int n=__shfl_up_sync(0xffffu,ix,o); if(tid>=o) ix+=n; }
                    I[16+tid]=ix-x;
                }
                __syncthreads();
                int rank=I[16+w]+v-c;
                for (int i=lo;i<hi;i++){
                    unsigned e=fenc(sc[i]);
                    int gt=(e>T), tie=(e==T);
                    g_sel[batch*Nn+i]=(gt||(tie&&rank<R))?1:0;
                    rank+=tie;
                }
            }
            __syncthreads();
            float c0v=g_c0;
            float lsum=0.f;
            for (int i=tid;i<Nn;i+=TPB){
                int g=batch*Nn+i;
                int s=g_sel[g]? g_soutdeg[g]:0;
                g_outdeg[g]=s;
                if (l==0) g_score[g]=c0v;
                int dc=s<1?1:s;
                lsum+=logf((float)dc+1.f);
                if (s>0){
                    int p=atomicAdd(&g_ngatedB[batch],1);
                    g_gatedB[batch*Nn+p]=g;
                    if (g_touched[g]==0){
                        g_touched[g]=1;
                        int q=atomicAdd(&g_ntouched,1);
                        g_touchedlist[q]=g;
                    }
                }
            }
            for (int o=16;o>0;o>>=1) lsum+=__shfl_down_sync(0xffffffffu,lsum,o);
            if (lane==0) F[w]=lsum;
            __syncthreads();
            if (tid==0){
                float v=0.f; for (int i=0;i<16;i++) v+=F[i];
                g_avgpart[batch]=v;
            }
        } else {
            float (*sh)[18]=(float(*)[18])S;
            int ntiles=(nt_old+15)/16;
            for (int tile=bid-Bq; tile<ntiles; tile+=GRID-Bq){
                int base=tile*16;
                if (tid<16) I[tid]=(base+tid<nt_old)? g_touchedlist[base+tid]:-1;
                __syncthreads();
                for (int jj=0;jj<4;jj++){
                    int j=hk*4+jj, node=I[j];
                    sh[lt][j]=(node>=0)? g_hidden[node*Dd+lt]:0.f;
                }
                __syncthreads();
                ull acc[4];
                #pragma unroll
                for (int p=0;p<4;p++) acc[p]=0ull;
                const float* wcol = preWl + (size_t)(hk>>1)*Dd*Dd;
                int pb0=(hk&1)*4;
                #pragma unroll 4
                for (int k=0;k<Dd;k++){
                    ull wd=f2dup(wcol[k*Dd+lt]);
                    #pragma unroll
                    for (int p=0;p<4;p++){
                        ull bv=*(const ull*)&sh[k][2*(pb0+p)];
                        fma2(acc[p],bv,wd);
                    }
                }
                float* dst=(hk>>1)? g_vtab:g_utab;
                #pragma unroll
                for (int p=0;p<4;p++){
                    float2 r=f2up(acc[p]);
                    int na=I[2*(pb0+p)], nb=I[2*(pb0+p)+1];
                    if (na>=0) dst[na*Dd+lt]=r.x;
                    if (nb>=0) dst[nb*Dd+lt]=r.y;
                }
                __syncthreads();
            }
        }
        GRIDBAR();

        // ---------- P8: tables [nt_old, nt_new) ----------
        {
            int nt_new = g_ntfrozen;
            int cnt = nt_new - nt_old;
            float (*sh)[18]=(float(*)[18])S;
            int ntiles=(cnt+15)/16;
            for (int tile=bid; tile<ntiles; tile+=GRID){
                int base=nt_old+tile*16;
                if (tid<16) I[tid]=(base+tid<nt_new)? g_touchedlist[base+tid]:-1;
                __syncthreads();
                for (int jj=0;jj<4;jj++){
                    int j=hk*4+jj, node=I[j];
                    sh[lt][j]=(node>=0)? g_hidden[node*Dd+lt]:0.f;
                }
                __syncthreads();
                ull acc[4];
                #pragma unroll
                for (int p=0;p<4;p++) acc[p]=0ull;
                const float* wcol = preWl + (size_t)(hk>>1)*Dd*Dd;
                int pb0=(hk&1)*4;
                #pragma unroll 4
                for (int k=0;k<Dd;k++){
                    ull wd=f2dup(wcol[k*Dd+lt]);
                    #pragma unroll
                    for (int p=0;p<4;p++){
                        ull bv=*(const ull*)&sh[k][2*(pb0+p)];
                        fma2(acc[p],bv,wd);
                    }
                }
                float* dst=(hk>>1)? g_vtab:g_utab;
                #pragma unroll
                for (int p=0;p<4;p++){
                    float2 r=f2up(acc[p]);
                    int na=I[2*(pb0+p)], nb=I[2*(pb0+p)+1];
                    if (na>=0) dst[na*Dd+lt]=r.x;
                    if (nb>=0) dst[nb*Dd+lt]=r.y;
                }
                __syncthreads();
            }
        }
        GRIDBAR();

        // ---------- P9: pna (warp-compacted agg + post/out GEMV + residual) ----------
        {
            float (*sbase)[18]=(float(*)[18])S;            // 512 rows
            float (*stmp)[18] =(float(*)[18])(S+9216);     // 128 rows
            int* slist=(int*)(S+9216);                     // alias stmp (disjoint in time)
            int n0=g_ngatedB[0], n1=g_ngatedB[1];
            int ng=n0+n1;
            float avg=(g_avgpart[0]+g_avgpart[1])/(float)BNq;
            float pbv=prebl[lt];
            int ntiles=(ng+15)/16;
            for (int tile=bid; tile<ntiles; tile+=GRID){
                int base=tile*16;
                if (tid<16){
                    int gi=base+tid, node=-1;
                    if (gi<ng) node=(gi<n0)? g_gatedB[gi] : g_gatedB[Nn+gi-n0];
                    I[tid]=node;
                    if (node>=0){
                        int dg=g_outdeg[node];
                        float logd=logf((float)(dg<1?1:dg)+1.f);
                        F[tid]=logd/avg; F[16+tid]=avg/logd;
                    } else { F[tid]=0.f; F[16+tid]=0.f; }
                }
                __syncthreads();
                // warp w compacts node I[w]'s selected in-srcs into slist[w*64..]
                {
                    int node=I[w]; int cnt=0;
                    if (node>=0){
                        int rs=g_rowptr[node], re=g_rowptr[node+1];
                        for (int b0=rs;b0<re;b0+=32){
                            int e=b0+lane; int a=0,s=0;
                            if (e<re){ s=g_col[e]; a=g_sel[s]; }
                            unsigned m=__ballot_sync(0xffffffffu,a);
                            if (a){
                                int pos=cnt+__popc(m&((1u<<lane)-1u));
                                if (pos<64) slist[w*64+pos]=s;
                            }
                            cnt+=__popc(m);
                        }
                        if (cnt>64) cnt=64;
                    }
                    if (lane==0) I[32+w]=cnt;
                }
                __syncthreads();
                // aggregation: 4 groups x 4 nodes, independent vtab loads
                for (int jj=0;jj<4;jj++){
                    int j=hk*4+jj, node=I[j];
                    float mean=0.f,mx=0.f,mn=0.f,sd=0.f;
                    if (node>=0){
                        float u=g_utab[node*Dd+lt]+pbv;
                        int cnt=I[32+j];
                        float s1=0.f,s2=0.f,vmx=-INFINITY,vmn=INFINITY;
                        #pragma unroll 4
                        for (int e=0;e<cnt;e++){
                            int s=slist[j*64+e];
                            float vv=g_touched[s]? g_vtab[s*Dd+lt]:0.f;
                            float m=u+vv;
                            s1+=m; s2+=m*m; vmx=fmaxf(vmx,m); vmn=fminf(vmn,m);
                        }
                        float denom=(cnt>0)?(float)cnt:1.f;
                        mean=s1/denom;
                        float var=fmaxf(s2/denom-mean*mean,0.f);
                        sd=sqrtf(var+EPSq);
                        mx=(cnt>0)?vmx:0.f; mn=(cnt>0)?vmn:0.f;
                    }
                    sbase[0*Dd+lt][j]=mean; sbase[1*Dd+lt][j]=mx;
                    sbase[2*Dd+lt][j]=mn;   sbase[3*Dd+lt][j]=sd;
                }
                __syncthreads();   // last slist read done; stmp region reusable
                ull z0[2],z1[2],z2[2];
                #pragma unroll
                for (int p=0;p<2;p++){ z0[p]=0ull; z1[p]=0ull; z2[p]=0ull; }
                #pragma unroll 2
                for (int k=0;k<4*Dd;k++){
                    ull w0=f2dup(postWl[k*Dd+lt]);
                    ull w1=f2dup(postWl[(4*Dd+k)*Dd+lt]);
                    ull w2=f2dup(postWl[(8*Dd+k)*Dd+lt]);
                    #pragma unroll
                    for (int p=0;p<2;p++){
                        int pp=hk*2+p;
                        ull bv=*(const ull*)&sbase[k][2*pp];
                        fma2(z0[p],bv,w0); fma2(z1[p],bv,w1); fma2(z2[p],bv,w2);
                    }
                }
                float pob=postbl[lt];
                #pragma unroll
                for (int p=0;p<2;p++){
                    int pp=hk*2+p;
                    float2 a=f2up(z0[p]), b=f2up(z1[p]), c=f2up(z2[p]);
                    stmp[lt][2*pp]  =pob+a.x+F[2*pp]*b.x  +F[16+2*pp]*c.x;
                    stmp[lt][2*pp+1]=pob+a.y+F[2*pp+1]*b.y+F[16+2*pp+1]*c.y;
                }
                __syncthreads();
                ull bb[2];
                #pragma unroll
                for (int p=0;p<2;p++) bb[p]=0ull;
                #pragma unroll 4
                for (int k=0;k<Dd;k++){
                    ull wd=f2dup(outWl[k*Dd+lt]);
                    #pragma unroll
                    for (int p=0;p<2;p++){
                        int pp=hk*2+p;
                        ull bv=*(const ull*)&stmp[k][2*pp];
                        fma2(bb[p],bv,wd);
                    }
                }
                float ob=outbl[lt];
                #pragma unroll
                for (int p=0;p<2;p++){
                    int pp=hk*2+p;
                    float2 r=f2up(bb[p]);
                    int na=I[2*pp], nb=I[2*pp+1];
                    if (na>=0) g_hidden[na*Dd+lt]+=ob+r.x;
                    if (nb>=0) g_hidden[nb*Dd+lt]+=ob+r.y;
                }
                __syncthreads();
            }
        }
        GRIDBAR();

        // ---------- P10: score ----------
        {
            float (*sh)[18]=(float(*)[18])S;
            float (*sx)[18]=(float(*)[18])(S+2304);
            float (*sp)[18]=(float(*)[18])(S+4608);
            float* part=S+6912;   // 512 floats
            int n0=g_ngatedB[0], n1=g_ngatedB[1];
            int cnt=(l==0)? g_ntfrozen : (n0+n1);
            float m2bv=m2b[0];
            int ntiles=(cnt+15)/16;
            for (int tile=bid; tile<ntiles; tile+=GRID){
                int base=tile*16;
                if (tid<16){
                    int gi=base+tid, node=-1;
                    if (gi<cnt){
                        if (l==0) node=g_touchedlist[gi];
                        else node=(gi<n0)? g_gatedB[gi] : g_gatedB[Nn+gi-n0];
                    }
                    I[tid]=node;
                }
                __syncthreads();
                for (int jj=0;jj<4;jj++){
                    int j=hk*4+jj, node=I[j];
                    sh[lt][j]=(node>=0)? g_hidden[node*Dd+lt]:0.f;
                }
                __syncthreads();
                ull aa[2];
                #pragma unroll
                for (int p=0;p<2;p++) aa[p]=0ull;
                #pragma unroll 4
                for (int k=0;k<Dd;k++){
                    ull wd=f2dup(linW[k*Dd+lt]);
                    #pragma unroll
                    for (int p=0;p<2;p++){
                        int pp=hk*2+p;
                        ull bv=*(const ull*)&sh[k][2*pp];
                        fma2(aa[p],bv,wd);
                    }
                }
                #pragma unroll
                for (int p=0;p<2;p++){
                    int pp=hk*2+p;
                    float2 a=f2up(aa[p]);
                    int na=I[2*pp], nb=I[2*pp+1];
                    float rA=(na>=0)? g_relc[(na/Nn)*Dd+lt]:0.f;
                    float rB=(nb>=0)? g_relc[(nb/Nn)*Dd+lt]:0.f;
                    sx[lt][2*pp]  =(a.x+rA)*sh[lt][2*pp];
                    sx[lt][2*pp+1]=(a.y+rB)*sh[lt][2*pp+1];
                }
                __syncthreads();
                ull hh[2];
                #pragma unroll
                for (int p=0;p<2;p++) hh[p]=0ull;
                #pragma unroll 4
                for (int k=0;k<Dd;k++){
                    ull wd=f2dup(m1W[k*Dd+lt]);
                    #pragma unroll
                    for (int p=0;p<2;p++){
                        int pp=hk*2+p;
                        ull bv=*(const ull*)&sx[k][2*pp];
                        fma2(hh[p],bv,wd);
                    }
                }
                float mb=m1b[lt], wm=m2W[lt];
                #pragma unroll
                for (int p=0;p<2;p++){
                    int pp=hk*2+p;
                    float2 h=f2up(hh[p]);
                    sp[lt][2*pp]  =fmaxf(h.x+mb,0.f)*wm;
                    sp[lt][2*pp+1]=fmaxf(h.y+mb,0.f)*wm;
                }
                __syncthreads();
                {
                    int j=tid>>5, seg=tid&31;
                    float s=0.f;
                    #pragma unroll
                    for (int k=seg*4;k<seg*4+4;k++) s+=sp[k][j];
                    part[tid]=s;
                }
                __syncthreads();
                if (tid<16 && I[tid]>=0){
                    float s=0.f;
                    for (int seg=0;seg<32;seg++) s+=part[tid*32+seg];
                    g_score[I[tid]]=s+m2bv;
                }
                __syncthreads();
            }
        }
        GRIDBAR();
    }

    if (bid==0 && tid<Bq*NEGq)
        out[tid] = g_score[g_tgather[tid]];

    #undef GRIDBAR
}

extern "C" void kernel_launch(void* const* d_in, const int* in_sizes, int n_in,
                              void* d_out, int out_size){
    (void)in_sizes; (void)n_in; (void)out_size;
    k_barinit<<<1,1>>>();
    k_mega<<<GRID, TPB>>>(
        (const int*)d_in[0], (const int*)d_in[1], (const int*)d_in[2],
        (const float*)d_in[3], (const int*)d_in[4], (const float*)d_in[5],
        (const float*)d_in[6], (const float*)d_in[7],
        (const float*)d_in[8], (const float*)d_in[9],
        (const float*)d_in[10], (const float*)d_in[11],
        (const float*)d_in[12], (const float*)d_in[13],
        (const float*)d_in[14], (const float*)d_in[15],
        (const float*)d_in[16], (const float*)d_in[17],
        (float*)d_out);
}

// round 13
// speedup vs baseline: 1.5435x; 1.1747x over previous
#include <cuda_runtime.h>
#include <math.h>

#define Bq 2
#define NEGq 16
#define Nn 10000
#define Ee 80000
#define Dd 128
#define NUMREL 237
#define Lq 3
#define Kq 1000
#define BNq (Bq*Nn)
#define BEq (Bq*Ee)
#define EPSq 1e-5f
#define GRID 148
#define TPB 1024
#define SCH 1024
#define NB2 ((BNq+SCH-1)/SCH)

typedef unsigned long long ull;

__device__ float g_hidden[BNq*Dd];
__device__ float g_score[BNq];
__device__ unsigned char g_sel[BNq];
__device__ int   g_outdeg[BNq];
__device__ int   g_soutdeg[BNq];
__device__ int   g_indeg[BNq];
__device__ int   g_rowptr[BNq+1];
__device__ int   g_col[BEq];
__device__ float g_utab[BNq*Dd];
__device__ float g_vtab[BNq*Dd];
__device__ int   g_gatedB[Bq*Nn];
__device__ int   g_ngatedB[Bq];
__device__ int   g_touchedlist[BNq];
__device__ unsigned char g_touched[BNq];
__device__ float g_rel[Bq*Dd];
__device__ float g_relc[Bq*Dd];
__device__ float g_hvals[Bq*Dd];
__device__ float g_tvals[Bq*Dd];
__device__ int   g_flat_h[Bq];
__device__ int   g_flat_t[Bq];
__device__ int   g_tgather[Bq*NEGq];
__device__ int   g_ntouched;
__device__ int   g_ntfrozen;
__device__ float g_avgpart[Bq];
__device__ float g_c0;
__device__ int   g_btot[64];
__device__ int   g_barcnt;
__device__ volatile int g_barepoch;

__device__ __forceinline__ unsigned fenc(float f){
    unsigned u = __float_as_uint(f);
    return (u & 0x80000000u) ? ~u : (u | 0x80000000u);
}
__device__ __forceinline__ ull f2pk(float lo, float hi){
    ull r; asm("mov.b64 %0, {%1,%2};" : "=l"(r) : "f"(lo), "f"(hi)); return r;
}
__device__ __forceinline__ ull f2dup(float w){ return f2pk(w,w); }
__device__ __forceinline__ void fma2(ull &d, ull a, ull b){
    asm("fma.rn.f32x2 %0, %1, %2, %0;" : "+l"(d) : "l"(a), "l"(b));
}
__device__ __forceinline__ float2 f2up(ull v){
    float lo, hi; asm("mov.b64 {%0,%1}, %2;" : "=f"(lo), "=f"(hi) : "l"(v));
    return make_float2(lo,hi);
}

__global__ void k_barinit(){
    g_barcnt = 0; g_barepoch = 0; g_ntfrozen = 0;
    __threadfence();
}

__global__ void __launch_bounds__(TPB)
k_mega(const int* __restrict__ h_index, const int* __restrict__ r_index,
       const int* __restrict__ t_index, const float* __restrict__ hidden_states,
       const int* __restrict__ edge_index, const float* __restrict__ rel_embedding,
       const float* __restrict__ linW, const float* __restrict__ linb,
       const float* __restrict__ m1W, const float* __restrict__ m1b,
       const float* __restrict__ m2W, const float* __restrict__ m2b,
       const float* __restrict__ preW, const float* __restrict__ preb,
       const float* __restrict__ postW, const float* __restrict__ postb,
       const float* __restrict__ outW, const float* __restrict__ outb,
       float* __restrict__ out)
{
    __shared__ __align__(16) float S[11520];
    __shared__ int   I[96];
    __shared__ float F[96];

    const int tid=threadIdx.x, bid=blockIdx.x;
    const int lane=tid&31, w=tid>>5;          // 32 warps
    const int lt=tid&127, hk=tid>>7;          // 8 groups of 128
    const int gid0=bid*TPB+tid, gstride=GRID*TPB;
    int epoch=0;

    #define GRIDBAR() do{ \
        __syncthreads(); \
        epoch++; \
        if (tid==0){ \
            __threadfence(); \
            if (atomicAdd(&g_barcnt,1)==GRID-1){ \
                g_barcnt=0; g_ntfrozen=g_ntouched; __threadfence(); g_barepoch=epoch; \
            } else { while (g_barepoch != epoch) __nanosleep(64); } \
            __threadfence(); \
        } \
        __syncthreads(); \
    }while(0)

    // ---------- P0: clear + setup ----------
    {
        float4 z4 = make_float4(0.f,0.f,0.f,0.f);
        for (int i=gid0; i<(BNq*Dd)/4; i+=gstride) ((float4*)g_hidden)[i]=z4;
        for (int i=gid0; i<BNq; i+=gstride){
            g_score[i]=0.f; g_touched[i]=0; g_indeg[i]=0; g_soutdeg[i]=0;
        }
        if (bid==0){
            if (tid < Bq){
                int b = tid;
                int h0 = h_index[b*NEGq];
                int neg = 1;
                for (int j=1;j<NEGq;j++) if (h_index[b*NEGq+j]!=h0) neg=0;
                int hh = neg ? h0 : t_index[b*NEGq];
                int tt = neg ? t_index[b*NEGq] : h0;
                int rr = neg ? r_index[b*NEGq] : r_index[b*NEGq] + NUMREL;
                I[tid]=hh; I[8+tid]=tt; I[16+tid]=rr; I[24+tid]=neg;
                g_flat_h[b] = hh + b*Nn;
                g_flat_t[b] = tt + b*Nn;
            }
            if (tid==0) g_ntouched = 0;
            __syncthreads();
            for (int idx=tid; idx<Bq*NEGq; idx+=TPB){
                int b = idx/NEGq;
                int tv = I[24+b] ? t_index[idx] : h_index[idx];
                g_tgather[idx] = tv + b*Nn;
            }
            for (int idx=tid; idx<Bq*Dd; idx+=TPB){
                int b = idx/Dd; int d = idx - b*Dd;
                g_rel[idx] = rel_embedding[I[16+b]*Dd + d];
                g_hvals[idx] = hidden_states[I[0]*Dd + d];   // repeat_interleave quirk -> row 0
                g_tvals[idx] = hidden_states[I[8]*Dd + d];
            }
            float v = (tid<Dd) ? fmaxf(m1b[tid],0.f)*m2W[tid] : 0.f;
            for (int o=16;o>0;o>>=1) v += __shfl_down_sync(0xffffffffu,v,o);
            if (lane==0) F[w]=v;
            __syncthreads();
            if (tid==0){
                float s=0.f; for(int i=0;i<32;i++) s+=F[i];
                g_c0 = s + m2b[0];
            }
        }
    }
    GRIDBAR();

    // ---------- P1: CSR count ----------
    for (int e=gid0; e<BEq; e+=gstride){
        int b = e/Ee, ei = e - b*Ee;
        atomicAdd(&g_indeg[edge_index[Ee+ei] + b*Nn], 1);
        atomicAdd(&g_soutdeg[edge_index[ei] + b*Nn], 1);
    }
    GRIDBAR();

    // ---------- P2: per-block local scan (1024/block) ----------
    if (bid < NB2){
        int i = bid*SCH + tid;
        int c = (i<BNq)? g_indeg[i]:0;
        int inc = c;
        for (int o=1;o<32;o<<=1){ int n=__shfl_up_sync(0xffffffffu,inc,o); if(lane>=o) inc+=n; }
        if (lane==31) I[w]=inc;
        __syncthreads();
        if (tid<32){
            int v=I[tid], iv=v;
            for (int o=1;o<32;o<<=1){ int n=__shfl_up_sync(0xffffffffu,iv,o); if(tid>=o) iv+=n; }
            I[32+tid]=iv-v;
            if (tid==31) g_btot[bid]=iv;
        }
        __syncthreads();
        int excl = I[32+w] + inc - c;
        if (i<BNq) g_rowptr[i]=excl;
    }
    GRIDBAR();

    // ---------- P4: offsets (inline btot scan) + fill cursor ----------
    {
        int* Bo=(int*)S;
        if (tid<NB2){ int s=0; for (int i=0;i<tid;i++) s+=g_btot[i]; Bo[tid]=s; }
        __syncthreads();
        for (int i=gid0; i<BNq; i+=gstride){
            int r = g_rowptr[i] + Bo[i/SCH];
            g_rowptr[i]=r; g_indeg[i]=r;
        }
        if (gid0==0) g_rowptr[BNq]=BEq;
    }
    GRIDBAR();

    // ---------- P5 (bid>=2): CSR fill  ||  P6 (bid 0,1): boundary+relc+init ----------
    if (bid >= 2){
        for (int e=(bid-2)*TPB+tid; e<BEq; e+=(GRID-2)*TPB){
            int b = e/Ee, ei = e - b*Ee;
            int s = edge_index[ei] + b*Nn;
            int d = edge_index[Ee+ei] + b*Nn;
            int pos = atomicAdd(&g_indeg[d],1);
            g_col[pos]=s;
        }
    } else {
        int b = bid;
        int fh = g_flat_h[b], ft = g_flat_t[b];
        if (tid<Dd){
            if (ft!=fh) g_hidden[ft*Dd+tid]=g_tvals[b*Dd+tid];
            g_hidden[fh*Dd+tid]=g_hvals[b*Dd+tid];
        }
        if (tid==0){
            int p=atomicAdd(&g_ntouched,1); g_touchedlist[p]=fh; g_touched[fh]=1;
            if (ft!=fh){ p=atomicAdd(&g_ntouched,1); g_touchedlist[p]=ft; g_touched[ft]=1; }
        }
        float *shv=S, *srl=S+128, *sxv=S+256, *spv=S+384;
        if (tid<Dd){ shv[tid]=g_hvals[b*Dd+tid]; srl[tid]=g_rel[b*Dd+tid]; }
        __syncthreads();
        if (tid<Dd){
            float rc=linb[tid];
            #pragma unroll 4
            for (int k=0;k<Dd;k++) rc += srl[k]*linW[(Dd+k)*Dd+tid];
            g_relc[b*Dd+tid]=rc;
            float acc=rc;
            #pragma unroll 4
            for (int k=0;k<Dd;k++) acc += shv[k]*linW[k*Dd+tid];
            sxv[tid]=acc*shv[tid];
        }
        __syncthreads();
        if (tid<Dd){
            float h=m1b[tid];
            #pragma unroll 4
            for (int k=0;k<Dd;k++) h += sxv[k]*m1W[k*Dd+tid];
            spv[tid]=fmaxf(h,0.f)*m2W[tid];
        }
        __syncthreads();
        if (tid==0){
            float s=0.f; for (int k=0;k<Dd;k++) s+=spv[k];
            g_score[fh]=s+m2b[0];
        }
    }
    GRIDBAR();

    // =================== layer loop ===================
    for (int l=0; l<Lq; l++){
        const float* preWl  = preW  + (size_t)l*2*Dd*Dd;
        const float* prebl  = preb  + (size_t)l*Dd;
        const float* postWl = postW + (size_t)l*12*Dd*Dd;
        const float* postbl = postb + (size_t)l*Dd;
        const float* outWl  = outW  + (size_t)l*Dd*Dd;
        const float* outbl  = outb  + (size_t)l*Dd;

        int nt_old = g_ntfrozen;

        // ---------- P7: selmark (bid 0,1) || tables [0,nt_old) (bid 2+) ----------
        if (bid < Bq){
            int batch = bid;
            unsigned* hist=(unsigned*)S;               // [0,4096)
            unsigned* ts  =(unsigned*)S+4096;          // [4096,5120)
            int* ws = (int*)((unsigned*)S+5120);       // 64 ints
            const float* sc = g_score + batch*Nn;
            if (tid==0){ I[88]=0; I[89]=0; g_ngatedB[batch]=0; }
            __syncthreads();
            for (int lvl=0;lvl<3;lvl++){
                for (int i=tid;i<4096;i+=TPB) hist[i]=0u;
                __syncthreads();
                unsigned p=(unsigned)I[88];
                const float4* sc4=(const float4*)sc;
                for (int i4=tid;i4<Nn/4;i4+=TPB){
                    float4 v4=sc4[i4];
                    float vv[4]={v4.x,v4.y,v4.z,v4.w};
                    #pragma unroll
                    for (int q=0;q<4;q++){
                        unsigned e=fenc(vv[q]); unsigned key; bool ok;
                        if (lvl==0){ ok=true;            key=e>>20; }
                        else if (lvl==1){ ok=((e>>20)==p); key=(e>>8)&0xFFFu; }
                        else            { ok=((e>>8)==p);  key=e&0xFFu; }
                        if (ok) atomicAdd(&hist[key],1u);
                    }
                }
                __syncthreads();
                unsigned tsum=hist[tid*4]+hist[tid*4+1]+hist[tid*4+2]+hist[tid*4+3];
                ts[tid]=tsum;
                unsigned wv=tsum;
                for (int o=16;o>0;o>>=1) wv+=__shfl_down_sync(0xffffffffu,wv,o);
                if (lane==0) ws[w]=(int)wv;
                __syncthreads();
                if (tid==0){
                    unsigned R=(unsigned)Kq-(unsigned)I[89];
                    unsigned acc=0u; int beta=0, wsel=0, tsel=0;
                    for (int ww=31;ww>=0;ww--){
                        if (acc+(unsigned)ws[ww]>=R){ wsel=ww; break; }
                        acc+=(unsigned)ws[ww];
                    }
                    for (int tt=wsel*32+31;tt>=wsel*32;tt--){
                        if (acc+ts[tt]>=R){ tsel=tt; break; }
                        acc+=ts[tt];
                    }
                    for (int b2=tsel*4+3;b2>=tsel*4;b2--){
                        if (acc+hist[b2]>=R){ beta=b2; break; }
                        acc+=hist[b2];
                    }
                    I[89]=(int)((unsigned)I[89]+acc);
                    unsigned sp=(unsigned)I[88];
                    I[88]=(int)((lvl==0)?(unsigned)beta:((sp<<((lvl==1)?12:8))|(unsigned)beta));
                }
                __syncthreads();
            }
            unsigned T=(unsigned)I[88]; int R=Kq-I[89];
            // two-pass contiguous mark (exact jax tie order: ascending index)
            {
                const int CH=(Nn+TPB-1)/TPB;   // 10
                int lo=tid*CH; if (lo>Nn) lo=Nn;
                int hi=lo+CH;  if (hi>Nn) hi=Nn;
                int c=0;
                for (int i=lo;i<hi;i++) c += (fenc(sc[i])==T);
                int v=c;
                for (int o=1;o<32;o<<=1){ int n=__shfl_up_sync(0xffffffffu,v,o); if(lane>=o) v+=n; }
                if (lane==31) ws[w]=v;
                __syncthreads();
                if (tid<32){
                    int x=ws[tid], ix=x;
                    for (int o=1;o<32;o<<=1){ int n=__shfl_up_sync(0xffffffffu,ix,o); if(tid>=o) ix+=n; }
                    ws[32+tid]=ix-x;
                }
                __syncthreads();
                int rank=ws[32+w]+v-c;
                for (int i=lo;i<hi;i++){
                    unsigned e=fenc(sc[i]);
                    int gt=(e>T), tie=(e==T);
                    g_sel[batch*Nn+i]=(gt||(tie&&rank<R))?1:0;
                    rank+=tie;
                }
            }
            __syncthreads();
            float c0v=g_c0;
            float lsum=0.f;
            for (int i=tid;i<Nn;i+=TPB){
                int g=batch*Nn+i;
                int s=g_sel[g]? g_soutdeg[g]:0;
                g_outdeg[g]=s;
                if (l==0) g_score[g]=c0v;
                int dc=s<1?1:s;
                lsum+=logf((float)dc+1.f);
                if (s>0){
                    int p=atomicAdd(&g_ngatedB[batch],1);
                    g_gatedB[batch*Nn+p]=g;
                    if (g_touched[g]==0){
                        g_touched[g]=1;
                        int q=atomicAdd(&g_ntouched,1);
                        g_touchedlist[q]=g;
                    }
                }
            }
            for (int o=16;o>0;o>>=1) lsum+=__shfl_down_sync(0xffffffffu,lsum,o);
            if (lane==0) F[w]=lsum;
            __syncthreads();
            if (tid==0){
                float v=0.f; for (int i=0;i<32;i++) v+=F[i];
                g_avgpart[batch]=v;
            }
        } else {
            // tables over [0, nt_old): groups 0-3 -> u (pairs (hk&3)*2..+1), 4-7 -> v
            float (*sh)[18]=(float(*)[18])S;
            int ntiles=(nt_old+15)/16;
            for (int tile=bid-Bq; tile<ntiles; tile+=GRID-Bq){
                int base=tile*16;
                if (tid<16) I[tid]=(base+tid<nt_old)? g_touchedlist[base+tid]:-1;
                __syncthreads();
                for (int jj=0;jj<2;jj++){
                    int j=hk*2+jj, node=I[j];
                    sh[lt][j]=(node>=0)? g_hidden[node*Dd+lt]:0.f;
                }
                __syncthreads();
                ull acc[2]; acc[0]=0ull; acc[1]=0ull;
                const float* wcol = preWl + (size_t)(hk>>2)*Dd*Dd;
                int pb0=(hk&3)*2;
                #pragma unroll 4
                for (int k=0;k<Dd;k++){
                    ull wd=f2dup(wcol[k*Dd+lt]);
                    fma2(acc[0],*(const ull*)&sh[k][2*pb0],wd);
                    fma2(acc[1],*(const ull*)&sh[k][2*(pb0+1)],wd);
                }
                float* dst=(hk>>2)? g_vtab:g_utab;
                #pragma unroll
                for (int p=0;p<2;p++){
                    float2 r=f2up(acc[p]);
                    int na=I[2*(pb0+p)], nb=I[2*(pb0+p)+1];
                    if (na>=0) dst[na*Dd+lt]=r.x;
                    if (nb>=0) dst[nb*Dd+lt]=r.y;
                }
                __syncthreads();
            }
        }
        GRIDBAR();

        // ---------- P8: tables [nt_old, nt_new) ----------
        {
            int nt_new = g_ntfrozen;
            int cnt = nt_new - nt_old;
            float (*sh)[18]=(float(*)[18])S;
            int ntiles=(cnt+15)/16;
            for (int tile=bid; tile<ntiles; tile+=GRID){
                int base=nt_old+tile*16;
                if (tid<16) I[tid]=(base+tid<nt_new)? g_touchedlist[base+tid]:-1;
                __syncthreads();
                for (int jj=0;jj<2;jj++){
                    int j=hk*2+jj, node=I[j];
                    sh[lt][j]=(node>=0)? g_hidden[node*Dd+lt]:0.f;
                }
                __syncthreads();
                ull acc[2]; acc[0]=0ull; acc[1]=0ull;
                const float* wcol = preWl + (size_t)(hk>>2)*Dd*Dd;
                int pb0=(hk&3)*2;
                #pragma unroll 4
                for (int k=0;k<Dd;k++){
                    ull wd=f2dup(wcol[k*Dd+lt]);
                    fma2(acc[0],*(const ull*)&sh[k][2*pb0],wd);
                    fma2(acc[1],*(const ull*)&sh[k][2*(pb0+1)],wd);
                }
                float* dst=(hk>>2)? g_vtab:g_utab;
                #pragma unroll
                for (int p=0;p<2;p++){
                    float2 r=f2up(acc[p]);
                    int na=I[2*(pb0+p)], nb=I[2*(pb0+p)+1];
                    if (na>=0) dst[na*Dd+lt]=r.x;
                    if (nb>=0) dst[nb*Dd+lt]=r.y;
                }
                __syncthreads();
            }
        }
        GRIDBAR();

        // ---------- P9: pna (warp-compacted agg + post/out GEMV + residual) ----------
        {
            float (*sbase)[18]=(float(*)[18])S;            // 512 rows
            float (*stmp)[18] =(float(*)[18])(S+9216);     // 128 rows
            int* slist=(int*)(S+9216);                     // alias stmp (disjoint in time)
            int n0=g_ngatedB[0], n1=g_ngatedB[1];
            int ng=n0+n1;
            float avg=(g_avgpart[0]+g_avgpart[1])/(float)BNq;
            float pbv=prebl[lt];
            int ntiles=(ng+15)/16;
            for (int tile=bid; tile<ntiles; tile+=GRID){
                int base=tile*16;
                if (tid<16){
                    int gi=base+tid, node=-1;
                    if (gi<ng) node=(gi<n0)? g_gatedB[gi] : g_gatedB[Nn+gi-n0];
                    I[tid]=node;
                    if (node>=0){
                        int dg=g_outdeg[node];
                        float logd=logf((float)(dg<1?1:dg)+1.f);
                        F[tid]=logd/avg; F[16+tid]=avg/logd;
                    } else { F[tid]=0.f; F[16+tid]=0.f; }
                }
                __syncthreads();
                // warps 0-15: warp w compacts node I[w]'s selected in-srcs
                if (w<16){
                    int node=I[w]; int cnt=0;
                    if (node>=0){
                        int rs=g_rowptr[node], re=g_rowptr[node+1];
                        for (int b0=rs;b0<re;b0+=32){
                            int e=b0+lane; int a=0,s=0;
                            if (e<re){ s=g_col[e]; a=g_sel[s]; }
                            unsigned m=__ballot_sync(0xffffffffu,a);
                            if (a){
                                int pos=cnt+__popc(m&((1u<<lane)-1u));
                                if (pos<64) slist[w*64+pos]=s;
                            }
                            cnt+=__popc(m);
                        }
                        if (cnt>64) cnt=64;
                    }
                    if (lane==0) I[32+w]=cnt;
                }
                __syncthreads();
                // aggregation: 8 groups x 2 nodes, independent vtab loads
                for (int jj=0;jj<2;jj++){
                    int j=hk*2+jj, node=I[j];
                    float mean=0.f,mx=0.f,mn=0.f,sd=0.f;
                    if (node>=0){
                        float u=g_utab[node*Dd+lt]+pbv;
                        int cnt=I[32+j];
                        float s1=0.f,s2=0.f,vmx=-INFINITY,vmn=INFINITY;
                        #pragma unroll 4
                        for (int e=0;e<cnt;e++){
                            int s=slist[j*64+e];
                            float vv=g_touched[s]? g_vtab[s*Dd+lt]:0.f;
                            float m=u+vv;
                            s1+=m; s2+=m*m; vmx=fmaxf(vmx,m); vmn=fminf(vmn,m);
                        }
                        float denom=(cnt>0)?(float)cnt:1.f;
                        mean=s1/denom;
                        float var=fmaxf(s2/denom-mean*mean,0.f);
                        sd=sqrtf(var+EPSq);
                        mx=(cnt>0)?vmx:0.f; mn=(cnt>0)?vmn:0.f;
                    }
                    sbase[0*Dd+lt][j]=mean; sbase[1*Dd+lt][j]=mx;
                    sbase[2*Dd+lt][j]=mn;   sbase[3*Dd+lt][j]=sd;
                }
                __syncthreads();   // last slist read done; stmp region reusable
                ull z0=0ull,z1=0ull,z2=0ull;
                #pragma unroll 4
                for (int k=0;k<4*Dd;k++){
                    ull bv=*(const ull*)&sbase[k][2*hk];
                    fma2(z0,bv,f2dup(postWl[k*Dd+lt]));
                    fma2(z1,bv,f2dup(postWl[(4*Dd+k)*Dd+lt]));
                    fma2(z2,bv,f2dup(postWl[(8*Dd+k)*Dd+lt]));
                }
                float pob=postbl[lt];
                {
                    float2 a=f2up(z0), b=f2up(z1), c=f2up(z2);
                    stmp[lt][2*hk]  =pob+a.x+F[2*hk]*b.x  +F[16+2*hk]*c.x;
                    stmp[lt][2*hk+1]=pob+a.y+F[2*hk+1]*b.y+F[16+2*hk+1]*c.y;
                }
                __syncthreads();
                ull bb=0ull;
                #pragma unroll 4
                for (int k=0;k<Dd;k++){
                    fma2(bb,*(const ull*)&stmp[k][2*hk],f2dup(outWl[k*Dd+lt]));
                }
                float ob=outbl[lt];
                {
                    float2 r=f2up(bb);
                    int na=I[2*hk], nb=I[2*hk+1];
                    if (na>=0) g_hidden[na*Dd+lt]+=ob+r.x;
                    if (nb>=0) g_hidden[nb*Dd+lt]+=ob+r.y;
                }
                __syncthreads();
            }
        }
        GRIDBAR();

        // ---------- P10: score ----------
        {
            float (*sh)[18]=(float(*)[18])S;
            float (*sx)[18]=(float(*)[18])(S+2304);
            float (*sp)[18]=(float(*)[18])(S+4608);
            float* part=S+6912;   // 1024 floats
            int n0=g_ngatedB[0], n1=g_ngatedB[1];
            int cnt=(l==0)? g_ntfrozen : (n0+n1);
            float m2bv=m2b[0];
            int ntiles=(cnt+15)/16;
            for (int tile=bid; tile<ntiles; tile+=GRID){
                int base=tile*16;
                if (tid<16){
                    int gi=base+tid, node=-1;
                    if (gi<cnt){
                        if (l==0) node=g_touchedlist[gi];
                        else node=(gi<n0)? g_gatedB[gi] : g_gatedB[Nn+gi-n0];
                    }
                    I[tid]=node;
                }
                __syncthreads();
                for (int jj=0;jj<2;jj++){
                    int j=hk*2+jj, node=I[j];
                    sh[lt][j]=(node>=0)? g_hidden[node*Dd+lt]:0.f;
                }
                __syncthreads();
                ull aa=0ull;
                #pragma unroll 4
                for (int k=0;k<Dd;k++){
                    fma2(aa,*(const ull*)&sh[k][2*hk],f2dup(linW[k*Dd+lt]));
                }
                {
                    float2 a=f2up(aa);
                    int na=I[2*hk], nb=I[2*hk+1];
                    float rA=(na>=0)? g_relc[(na/Nn)*Dd+lt]:0.f;
                    float rB=(nb>=0)? g_relc[(nb/Nn)*Dd+lt]:0.f;
                    sx[lt][2*hk]  =(a.x+rA)*sh[lt][2*hk];
                    sx[lt][2*hk+1]=(a.y+rB)*sh[lt][2*hk+1];
                }
                __syncthreads();
                ull hh=0ull;
                #pragma unroll 4
                for (int k=0;k<Dd;k++){
                    fma2(hh,*(const ull*)&sx[k][2*hk],f2dup(m1W[k*Dd+lt]));
                }
                float mb=m1b[lt], wm=m2W[lt];
                {
                    float2 h=f2up(hh);
                    sp[lt][2*hk]  =fmaxf(h.x+mb,0.f)*wm;
                    sp[lt][2*hk+1]=fmaxf(h.y+mb,0.f)*wm;
                }
                __syncthreads();
                {
                    int j=tid>>6, seg=tid&63;
                    part[tid]=sp[seg*2][j]+sp[seg*2+1][j];
                }
                __syncthreads();
                if (tid<16 && I[tid]>=0){
                    float s=0.f;
                    for (int seg=0;seg<64;seg++) s+=part[tid*64+seg];
                    g_score[I[tid]]=s+m2bv;
                }
                __syncthreads();
            }
        }
        GRIDBAR();
    }

    if (bid==0 && tid<Bq*NEGq)
        out[tid] = g_score[g_tgather[tid]];

    #undef GRIDBAR
}

extern "C" void kernel_launch(void* const* d_in, const int* in_sizes, int n_in,
                              void* d_out, int out_size){
    (void)in_sizes; (void)n_in; (void)out_size;
    k_barinit<<<1,1>>>();
    k_mega<<<GRID, TPB>>>(
        (const int*)d_in[0], (const int*)d_in[1], (const int*)d_in[2],
        (const float*)d_in[3], (const int*)d_in[4], (const float*)d_in[5],
        (const float*)d_in[6], (const float*)d_in[7],
        (const float*)d_in[8], (const float*)d_in[9],
        (const float*)d_in[10], (const float*)d_in[11],
        (const float*)d_in[12], (const float*)d_in[13],
        (const float*)d_in[14], (const float*)d_in[15],
        (const float*)d_in[16], (const float*)d_in[17],
        (float*)d_out);
}

// round 15
// speedup vs baseline: 2.1935x; 1.4211x over previous
#include <cuda_runtime.h>
#include <math.h>

#define Bq 2
#define NEGq 16
#define Nn 10000
#define Ee 80000
#define Dd 128
#define NUMREL 237
#define Lq 3
#define Kq 1000
#define BNq (Bq*Nn)
#define BEq (Bq*Ee)
#define EPSq 1e-5f
#define GRID 148
#define TPB 1024
#define SCH 1024
#define NB2 ((BNq+SCH-1)/SCH)
#define SMEMSZ 65536

typedef unsigned long long ull;

__device__ float g_hidden[BNq*Dd];
__device__ float g_score[BNq];
__device__ unsigned char g_sel[BNq];
__device__ int   g_outdeg[BNq];
__device__ int   g_soutdeg[BNq];
__device__ int   g_indeg[BNq];
__device__ int   g_rowptr[BNq+1];
__device__ int   g_col[BEq];
__device__ float g_utab[BNq*Dd];
__device__ float g_vtab[BNq*Dd];
__device__ int   g_gatedB[Bq*Nn];
__device__ int   g_ngatedB[Bq];
__device__ int   g_touchedlist[BNq];
__device__ unsigned char g_touched[BNq];
__device__ unsigned char g_tabbed[BNq];   // table computed from current-layer input hidden
__device__ float g_rel[Bq*Dd];
__device__ float g_relc[Bq*Dd];
__device__ float g_hvals[Bq*Dd];
__device__ float g_tvals[Bq*Dd];
__device__ int   g_flat_h[Bq];
__device__ int   g_flat_t[Bq];
__device__ int   g_tgather[Bq*NEGq];
__device__ int   g_ntouched;
__device__ int   g_ntfrozen;
__device__ float g_avgpart[Bq];
__device__ float g_c0;
__device__ int   g_btot[64];
__device__ int   g_barcnt;
__device__ volatile int g_barepoch;

__device__ __forceinline__ unsigned fenc(float f){
    unsigned u = __float_as_uint(f);
    return (u & 0x80000000u) ? ~u : (u | 0x80000000u);
}
__device__ __forceinline__ ull f2pk(float lo, float hi){
    ull r; asm("mov.b64 %0, {%1,%2};" : "=l"(r) : "f"(lo), "f"(hi)); return r;
}
__device__ __forceinline__ ull f2dup(float w){ return f2pk(w,w); }
__device__ __forceinline__ void fma2(ull &d, ull a, ull b){
    asm("fma.rn.f32x2 %0, %1, %2, %0;" : "+l"(d) : "l"(a), "l"(b));
}
__device__ __forceinline__ float2 f2up(ull v){
    float lo, hi; asm("mov.b64 {%0,%1}, %2;" : "=f"(lo), "=f"(hi) : "l"(v));
    return make_float2(lo,hi);
}

__global__ void k_barinit(){
    g_barcnt = 0; g_barepoch = 0; g_ntfrozen = 0;
    __threadfence();
}

__global__ void __launch_bounds__(TPB)
k_mega(const int* __restrict__ h_index, const int* __restrict__ r_index,
       const int* __restrict__ t_index, const float* __restrict__ hidden_states,
       const int* __restrict__ edge_index, const float* __restrict__ rel_embedding,
       const float* __restrict__ linW, const float* __restrict__ linb,
       const float* __restrict__ m1W, const float* __restrict__ m1b,
       const float* __restrict__ m2W, const float* __restrict__ m2b,
       const float* __restrict__ preW, const float* __restrict__ preb,
       const float* __restrict__ postW, const float* __restrict__ postb,
       const float* __restrict__ outW, const float* __restrict__ outb,
       float* __restrict__ out)
{
    extern __shared__ __align__(16) float DS[];   // 65536 B dynamic
    __shared__ int   I[96];
    __shared__ float F[96];

    const int tid=threadIdx.x, bid=blockIdx.x;
    const int lane=tid&31, w=tid>>5;          // 32 warps
    const int lt=tid&127, hk=tid>>7;          // 8 groups of 128
    const int gid0=bid*TPB+tid, gstride=GRID*TPB;
    int epoch=0;

    #define GRIDBAR() do{ \
        __syncthreads(); \
        epoch++; \
        if (tid==0){ \
            __threadfence(); \
            if (atomicAdd(&g_barcnt,1)==GRID-1){ \
                g_barcnt=0; g_ntfrozen=g_ntouched; __threadfence(); g_barepoch=epoch; \
            } else { while (g_barepoch != epoch) __nanosleep(64); } \
            __threadfence(); \
        } \
        __syncthreads(); \
    }while(0)

    // ---------- P0: clear + setup ----------
    {
        float4 z4 = make_float4(0.f,0.f,0.f,0.f);
        for (int i=gid0; i<(BNq*Dd)/4; i+=gstride) ((float4*)g_hidden)[i]=z4;
        for (int i=gid0; i<BNq; i+=gstride){
            g_score[i]=0.f; g_touched[i]=0; g_tabbed[i]=0; g_indeg[i]=0; g_soutdeg[i]=0;
        }
        if (bid==0){
            if (tid < Bq){
                int b = tid;
                int h0 = h_index[b*NEGq];
                int neg = 1;
                for (int j=1;j<NEGq;j++) if (h_index[b*NEGq+j]!=h0) neg=0;
                int hh = neg ? h0 : t_index[b*NEGq];
                int tt = neg ? t_index[b*NEGq] : h0;
                int rr = neg ? r_index[b*NEGq] : r_index[b*NEGq] + NUMREL;
                I[tid]=hh; I[8+tid]=tt; I[16+tid]=rr; I[24+tid]=neg;
                g_flat_h[b] = hh + b*Nn;
                g_flat_t[b] = tt + b*Nn;
            }
            if (tid==0) g_ntouched = 0;
            __syncthreads();
            for (int idx=tid; idx<Bq*NEGq; idx+=TPB){
                int b = idx/NEGq;
                int tv = I[24+b] ? t_index[idx] : h_index[idx];
                g_tgather[idx] = tv + b*Nn;
            }
            for (int idx=tid; idx<Bq*Dd; idx+=TPB){
                int b = idx/Dd; int d = idx - b*Dd;
                g_rel[idx] = rel_embedding[I[16+b]*Dd + d];
                g_hvals[idx] = hidden_states[I[0]*Dd + d];   // repeat_interleave quirk -> row 0
                g_tvals[idx] = hidden_states[I[8]*Dd + d];
            }
            float v = (tid<Dd) ? fmaxf(m1b[tid],0.f)*m2W[tid] : 0.f;
            for (int o=16;o>0;o>>=1) v += __shfl_down_sync(0xffffffffu,v,o);
            if (lane==0) F[w]=v;
            __syncthreads();
            if (tid==0){
                float s=0.f; for(int i=0;i<32;i++) s+=F[i];
                g_c0 = s + m2b[0];
            }
        }
    }
    GRIDBAR();

    // ---------- P1: CSR count ----------
    for (int e=gid0; e<BEq; e+=gstride){
        int b = e/Ee, ei = e - b*Ee;
        atomicAdd(&g_indeg[edge_index[Ee+ei] + b*Nn], 1);
        atomicAdd(&g_soutdeg[edge_index[ei] + b*Nn], 1);
    }
    GRIDBAR();

    // ---------- P2: per-block local scan (1024/block) ----------
    if (bid < NB2){
        int i = bid*SCH + tid;
        int c = (i<BNq)? g_indeg[i]:0;
        int inc = c;
        for (int o=1;o<32;o<<=1){ int n=__shfl_up_sync(0xffffffffu,inc,o); if(lane>=o) inc+=n; }
        if (lane==31) I[w]=inc;
        __syncthreads();
        if (tid<32){
            int v=I[tid], iv=v;
            for (int o=1;o<32;o<<=1){ int n=__shfl_up_sync(0xffffffffu,iv,o); if(tid>=o) iv+=n; }
            I[32+tid]=iv-v;
            if (tid==31) g_btot[bid]=iv;
        }
        __syncthreads();
        int excl = I[32+w] + inc - c;
        if (i<BNq) g_rowptr[i]=excl;
    }
    GRIDBAR();

    // ---------- P4: offsets + fill cursor ----------
    {
        int* Bo=(int*)DS;
        if (tid<NB2){ int s=0; for (int i=0;i<tid;i++) s+=g_btot[i]; Bo[tid]=s; }
        __syncthreads();
        for (int i=gid0; i<BNq; i+=gstride){
            int r = g_rowptr[i] + Bo[i/SCH];
            g_rowptr[i]=r; g_indeg[i]=r;
        }
        if (gid0==0) g_rowptr[BNq]=BEq;
    }
    GRIDBAR();

    // ---------- P5 (bid>=2): CSR fill  ||  P6 (bid 0,1): boundary+relc+init ----------
    if (bid >= 2){
        for (int e=(bid-2)*TPB+tid; e<BEq; e+=(GRID-2)*TPB){
            int b = e/Ee, ei = e - b*Ee;
            int s = edge_index[ei] + b*Nn;
            int d = edge_index[Ee+ei] + b*Nn;
            int pos = atomicAdd(&g_indeg[d],1);
            g_col[pos]=s;
        }
    } else {
        int b = bid;
        int fh = g_flat_h[b], ft = g_flat_t[b];
        if (tid<Dd){
            if (ft!=fh) g_hidden[ft*Dd+tid]=g_tvals[b*Dd+tid];
            g_hidden[fh*Dd+tid]=g_hvals[b*Dd+tid];
        }
        if (tid==0){
            int p=atomicAdd(&g_ntouched,1); g_touchedlist[p]=fh; g_touched[fh]=1;
            if (ft!=fh){ p=atomicAdd(&g_ntouched,1); g_touchedlist[p]=ft; g_touched[ft]=1; }
        }
        float *shv=DS, *srl=DS+128, *sxv=DS+256, *spv=DS+384;
        if (tid<Dd){ shv[tid]=g_hvals[b*Dd+tid]; srl[tid]=g_rel[b*Dd+tid]; }
        __syncthreads();
        if (tid<Dd){
            float rc=linb[tid];
            #pragma unroll 4
            for (int k=0;k<Dd;k++) rc += srl[k]*linW[(Dd+k)*Dd+tid];
            g_relc[b*Dd+tid]=rc;
            float acc=rc;
            #pragma unroll 4
            for (int k=0;k<Dd;k++) acc += shv[k]*linW[k*Dd+tid];
            sxv[tid]=acc*shv[tid];
        }
        __syncthreads();
        if (tid<Dd){
            float h=m1b[tid];
            #pragma unroll 4
            for (int k=0;k<Dd;k++) h += sxv[k]*m1W[k*Dd+tid];
            spv[tid]=fmaxf(h,0.f)*m2W[tid];
        }
        __syncthreads();
        if (tid==0){
            float s=0.f; for (int k=0;k<Dd;k++) s+=spv[k];
            g_score[fh]=s+m2b[0];
        }
    }
    GRIDBAR();

    const float mb=m1b[lt], wm=m2W[lt], m2bv=m2b[0];

    // =================== layer loop ===================
    for (int l=0; l<Lq; l++){
        const float* preWl  = preW  + (size_t)l*2*Dd*Dd;
        const float* prebl  = preb  + (size_t)l*Dd;
        const float* postWl = postW + (size_t)l*12*Dd*Dd;
        const float* postbl = postb + (size_t)l*Dd;
        const float* outWl  = outW  + (size_t)l*Dd*Dd;
        const float* outbl  = outb  + (size_t)l*Dd;

        int nt_old = g_ntfrozen;

        // ---------- P7: selmark (bid 0,1) || tables [0,nt_old) (bid 2+) ----------
        if (bid < Bq){
            int batch = bid;
            unsigned* hist=(unsigned*)DS;
            unsigned* ts  =(unsigned*)DS+4096;
            int* ws = (int*)((unsigned*)DS+5120);
            const float* sc = g_score + batch*Nn;
            if (tid==0){ I[88]=0; I[89]=0; g_ngatedB[batch]=0; }
            __syncthreads();
            for (int lvl=0;lvl<3;lvl++){
                for (int i=tid;i<4096;i+=TPB) hist[i]=0u;
                __syncthreads();
                unsigned p=(unsigned)I[88];
                const float4* sc4=(const float4*)sc;
                for (int i4=tid;i4<Nn/4;i4+=TPB){
                    float4 v4=sc4[i4];
                    float vv[4]={v4.x,v4.y,v4.z,v4.w};
                    #pragma unroll
                    for (int q=0;q<4;q++){
                        unsigned e=fenc(vv[q]); unsigned key; bool ok;
                        if (lvl==0){ ok=true;            key=e>>20; }
                        else if (lvl==1){ ok=((e>>20)==p); key=(e>>8)&0xFFFu; }
                        else            { ok=((e>>8)==p);  key=e&0xFFu; }
                        if (ok) atomicAdd(&hist[key],1u);
                    }
                }
                __syncthreads();
                unsigned tsum=hist[tid*4]+hist[tid*4+1]+hist[tid*4+2]+hist[tid*4+3];
                ts[tid]=tsum;
                unsigned wv=tsum;
                for (int o=16;o>0;o>>=1) wv+=__shfl_down_sync(0xffffffffu,wv,o);
                if (lane==0) ws[w]=(int)wv;
                __syncthreads();
                if (tid==0){
                    unsigned R=(unsigned)Kq-(unsigned)I[89];
                    unsigned acc=0u; int beta=0, wsel=0, tsel=0;
                    for (int ww=31;ww>=0;ww--){
                        if (acc+(unsigned)ws[ww]>=R){ wsel=ww; break; }
                        acc+=(unsigned)ws[ww];
                    }
                    for (int tt=wsel*32+31;tt>=wsel*32;tt--){
                        if (acc+ts[tt]>=R){ tsel=tt; break; }
                        acc+=ts[tt];
                    }
                    for (int b2=tsel*4+3;b2>=tsel*4;b2--){
                        if (acc+hist[b2]>=R){ beta=b2; break; }
                        acc+=hist[b2];
                    }
                    I[89]=(int)((unsigned)I[89]+acc);
                    unsigned sp=(unsigned)I[88];
                    I[88]=(int)((lvl==0)?(unsigned)beta:((sp<<((lvl==1)?12:8))|(unsigned)beta));
                }
                __syncthreads();
            }
            unsigned T=(unsigned)I[88]; int R=Kq-I[89];
            {   // two-pass contiguous mark (jax tie order: ascending index)
                const int CH=(Nn+TPB-1)/TPB;
                int lo=tid*CH; if (lo>Nn) lo=Nn;
                int hi=lo+CH;  if (hi>Nn) hi=Nn;
                int c=0;
                for (int i=lo;i<hi;i++) c += (fenc(sc[i])==T);
                int v=c;
                for (int o=1;o<32;o<<=1){ int n=__shfl_up_sync(0xffffffffu,v,o); if(lane>=o) v+=n; }
                if (lane==31) ws[w]=v;
                __syncthreads();
                if (tid<32){
                    int x=ws[tid], ix=x;
                    for (int o=1;o<32;o<<=1){ int n=__shfl_up_sync(0xffffffffu,ix,o); if(tid>=o) ix+=n; }
                    ws[32+tid]=ix-x;
                }
                __syncthreads();
                int rank=ws[32+w]+v-c;
                for (int i=lo;i<hi;i++){
                    unsigned e=fenc(sc[i]);
                    int gt=(e>T), tie=(e==T);
                    g_sel[batch*Nn+i]=(gt||(tie&&rank<R))?1:0;
                    rank+=tie;
                }
            }
            __syncthreads();
            float c0v=g_c0;
            float lsum=0.f;
            for (int i=tid;i<Nn;i+=TPB){
                int g=batch*Nn+i;
                int s=g_sel[g]? g_soutdeg[g]:0;
                g_outdeg[g]=s;
                if (l==0) g_score[g]=c0v;
                int dc=s<1?1:s;
                lsum+=logf((float)dc+1.f);
                if (s>0){
                    int p=atomicAdd(&g_ngatedB[batch],1);
                    g_gatedB[batch*Nn+p]=g;
                    if (g_touched[g]==0){
                        g_touched[g]=1;
                        int q=atomicAdd(&g_ntouched,1);
                        g_touchedlist[q]=g;
                    }
                }
            }
            for (int o=16;o>0;o>>=1) lsum+=__shfl_down_sync(0xffffffffu,lsum,o);
            if (lane==0) F[w]=lsum;
            __syncthreads();
            if (tid==0){
                float v=0.f; for (int i=0;i<32;i++) v+=F[i];
                g_avgpart[batch]=v;
            }
        } else {
            // tables over [0, nt_old) : groups 0-3 -> u, 4-7 -> v; set tabbed
            float* sh = DS;                      // [128][16]
            int ntiles=(nt_old+15)/16;
            for (int tile=bid-Bq; tile<ntiles; tile+=GRID-Bq){
                int base=tile*16;
                if (tid<16){
                    int node=(base+tid<nt_old)? g_touchedlist[base+tid]:-1;
                    I[tid]=node;
                    if (node>=0) g_tabbed[node]=1;
                }
                __syncthreads();
                for (int jj=0;jj<2;jj++){
                    int j=hk*2+jj, node=I[j];
                    sh[lt*16+j]=(node>=0)? g_hidden[node*Dd+lt]:0.f;
                }
                __syncthreads();
                ull acc0=0ull, acc1=0ull;
                const float* wcol = preWl + (size_t)(hk>>2)*Dd*Dd;
                int pb0=(hk&3)*2;
                #pragma unroll 4
                for (int k=0;k<Dd;k++){
                    ull wd=f2dup(wcol[k*Dd+lt]);
                    fma2(acc0,*(const ull*)&sh[k*16+2*pb0],wd);
                    fma2(acc1,*(const ull*)&sh[k*16+2*(pb0+1)],wd);
                }
                float* dst=(hk>>2)? g_vtab:g_utab;
                {
                    float2 r=f2up(acc0);
                    int na=I[2*pb0], nb=I[2*pb0+1];
                    if (na>=0) dst[na*Dd+lt]=r.x;
                    if (nb>=0) dst[nb*Dd+lt]=r.y;
                    r=f2up(acc1);
                    na=I[2*(pb0+1)]; nb=I[2*(pb0+1)+1];
                    if (na>=0) dst[na*Dd+lt]=r.x;
                    if (nb>=0) dst[nb*Dd+lt]=r.y;
                }
                __syncthreads();
            }
        }
        GRIDBAR();

        // ---------- P9: agg + split-k post/out + residual + fused split-k score ----------
        {
            float* A  = DS;                 // 8192 floats: sbase[512][16], later stmp/snh/sx/sp
            ull*   P  = (ull*)(DS+8192);    // 4096 ull partials
            int*   slist=(int*)P;           // 16*128 ints during compaction
            float* Pf = (float*)P;
            int n0=g_ngatedB[0], n1=g_ngatedB[1];
            int ng=n0+n1;
            float avg=(g_avgpart[0]+g_avgpart[1])/(float)BNq;
            float pbv=prebl[lt];
            const int ks=hk&3, nh=hk>>2;
            int ntg=(ng+15)/16;
            int ntiles=ntg+((l==0)?1:0);
            for (int tile=bid; tile<ntiles; tile+=GRID){
                if (tile<ntg){
                    int base=tile*16;
                    if (tid<16){
                        int gi=base+tid, node=-1;
                        if (gi<ng) node=(gi<n0)? g_gatedB[gi] : g_gatedB[Nn+gi-n0];
                        I[tid]=node;
                        if (node>=0){
                            int dg=g_outdeg[node];
                            float logd=logf((float)(dg<1?1:dg)+1.f);
                            F[tid]=logd/avg; F[16+tid]=avg/logd;
                        } else { F[tid]=0.f; F[16+tid]=0.f; }
                    }
                    __syncthreads();
                    // warps 0-15: compact selected in-srcs of node I[w]
                    if (w<16){
                        int node=I[w]; int cnt=0;
                        if (node>=0){
                            int rs=g_rowptr[node], re=g_rowptr[node+1];
                            for (int b0=rs;b0<re;b0+=32){
                                int e=b0+lane; int a=0,s=0;
                                if (e<re){ s=g_col[e]; a=g_sel[s]; }
                                unsigned m=__ballot_sync(0xffffffffu,a);
                                if (a){
                                    int pos=cnt+__popc(m&((1u<<lane)-1u));
                                    if (pos<128) slist[w*128+pos]=s;
                                }
                                cnt+=__popc(m);
                            }
                            if (cnt>128) cnt=128;
                        }
                        if (lane==0) I[32+w]=cnt;
                    }
                    __syncthreads();
                    // aggregation: 8 groups x 2 nodes
                    for (int jj=0;jj<2;jj++){
                        int j=hk*2+jj, node=I[j];
                        float mean=0.f,mx=0.f,mn=0.f,sd=0.f;
                        if (node>=0){
                            float u=(g_tabbed[node]? g_utab[node*Dd+lt]:0.f)+pbv;
                            int cnt=I[32+j];
                            float s1=0.f,s2=0.f,vmx=-INFINITY,vmn=INFINITY;
                            #pragma unroll 4
                            for (int e=0;e<cnt;e++){
                                int s=slist[j*128+e];
                                float vv=g_tabbed[s]? g_vtab[s*Dd+lt]:0.f;
                                float m=u+vv;
                                s1+=m; s2+=m*m; vmx=fmaxf(vmx,m); vmn=fminf(vmn,m);
                            }
                            float denom=(cnt>0)?(float)cnt:1.f;
                            mean=s1/denom;
                            float var=fmaxf(s2/denom-mean*mean,0.f);
                            sd=sqrtf(var+EPSq);
                            mx=(cnt>0)?vmx:0.f; mn=(cnt>0)?vmn:0.f;
                        }
                        A[(0*Dd+lt)*16+j]=mean; A[(1*Dd+lt)*16+j]=mx;
                        A[(2*Dd+lt)*16+j]=mn;   A[(3*Dd+lt)*16+j]=sd;
                    }
                    __syncthreads();
                    // post GEMV split-k: group (ks,nh), k-slice 128, pairs nh*4..+3
                    {
                        ull z0[4],z1[4],z2[4];
                        #pragma unroll
                        for (int p=0;p<4;p++){ z0[p]=0ull; z1[p]=0ull; z2[p]=0ull; }
                        int kb=ks*128;
                        #pragma unroll 2
                        for (int kk=0;kk<128;kk++){
                            int k=kb+kk;
                            ull w0=f2dup(postWl[k*Dd+lt]);
                            ull w1=f2dup(postWl[(4*Dd+k)*Dd+lt]);
                            ull w2=f2dup(postWl[(8*Dd+k)*Dd+lt]);
                            #pragma unroll
                            for (int p=0;p<4;p++){
                                ull bv=*(const ull*)&A[k*16+2*(nh*4+p)];
                                fma2(z0[p],bv,w0); fma2(z1[p],bv,w1); fma2(z2[p],bv,w2);
                            }
                        }
                        #pragma unroll
                        for (int p=0;p<4;p++){
                            int j=nh*4+p;
                            float2 a=f2up(z0[p]), b=f2up(z1[p]), c=f2up(z2[p]);
                            float wx=a.x+F[2*j]*b.x+F[16+2*j]*c.x;
                            float wy=a.y+F[2*j+1]*b.y+F[16+2*j+1]*c.y;
                            P[(ks*128+lt)*8+j]=f2pk(wx,wy);
                        }
                    }
                    __syncthreads();
                    // reduce -> stmp (A[0..2048)): thread (hk,lt) holds pair hk
                    {
                        float pob=postbl[lt];
                        float ax=pob, ay=pob;
                        #pragma unroll
                        for (int q=0;q<4;q++){ float2 t=f2up(P[(q*128+lt)*8+hk]); ax+=t.x; ay+=t.y; }
                        *(ull*)&A[lt*16+2*hk]=f2pk(ax,ay);
                    }
                    __syncthreads();
                    // out GEMV split-k (k-slice 32)
                    {
                        ull o4[4];
                        #pragma unroll
                        for (int p=0;p<4;p++) o4[p]=0ull;
                        int kb=ks*32;
                        #pragma unroll 4
                        for (int kk=0;kk<32;kk++){
                            int k=kb+kk;
                            ull wd=f2dup(outWl[k*Dd+lt]);
                            #pragma unroll
                            for (int p=0;p<4;p++){
                                ull bv=*(const ull*)&A[k*16+2*(nh*4+p)];
                                fma2(o4[p],bv,wd);
                            }
                        }
                        #pragma unroll
                        for (int p=0;p<4;p++) P[(ks*128+lt)*8+(nh*4+p)]=o4[p];
                    }
                    __syncthreads();
                    // reduce + residual + snh (A[2048..4096))
                    {
                        float ob=outbl[lt];
                        float ax=ob, ay=ob;
                        #pragma unroll
                        for (int q=0;q<4;q++){ float2 t=f2up(P[(q*128+lt)*8+hk]); ax+=t.x; ay+=t.y; }
                        int na=I[2*hk], nb=I[2*hk+1];
                        float hx=0.f, hy=0.f;
                        if (na>=0){ hx=g_hidden[na*Dd+lt]+ax; g_hidden[na*Dd+lt]=hx; }
                        if (nb>=0){ hy=g_hidden[nb*Dd+lt]+ay; g_hidden[nb*Dd+lt]=hy; }
                        *(ull*)&A[2048+lt*16+2*hk]=f2pk(hx,hy);
                    }
                    __syncthreads();
                    // lin GEMV split-k over snh
                    {
                        ull a4[4];
                        #pragma unroll
                        for (int p=0;p<4;p++) a4[p]=0ull;
                        int kb=ks*32;
                        #pragma unroll 4
                        for (int kk=0;kk<32;kk++){
                            int k=kb+kk;
                            ull wd=f2dup(linW[k*Dd+lt]);
                            #pragma unroll
                            for (int p=0;p<4;p++){
                                ull bv=*(const ull*)&A[2048+k*16+2*(nh*4+p)];
                                fma2(a4[p],bv,wd);
                            }
                        }
                        #pragma unroll
                        for (int p=0;p<4;p++) P[(ks*128+lt)*8+(nh*4+p)]=a4[p];
                    }
                    __syncthreads();
                    // reduce -> sx (A[4096..6144))
                    {
                        float ax=0.f, ay=0.f;
                        #pragma unroll
                        for (int q=0;q<4;q++){ float2 t=f2up(P[(q*128+lt)*8+hk]); ax+=t.x; ay+=t.y; }
                        int na=I[2*hk], nb=I[2*hk+1];
                        float rA=(na>=0)? g_relc[(na/Nn)*Dd+lt]:0.f;
                        float rB=(nb>=0)? g_relc[(nb/Nn)*Dd+lt]:0.f;
                        *(ull*)&A[4096+lt*16+2*hk]=
                            f2pk((ax+rA)*A[2048+lt*16+2*hk],(ay+rB)*A[2048+lt*16+2*hk+1]);
                    }
                    __syncthreads();
                    // m1 GEMV split-k over sx
                    {
                        ull m4[4];
                        #pragma unroll
                        for (int p=0;p<4;p++) m4[p]=0ull;
                        int kb=ks*32;
                        #pragma unroll 4
                        for (int kk=0;kk<32;kk++){
                            int k=kb+kk;
                            ull wd=f2dup(m1W[k*Dd+lt]);
                            #pragma unroll
                            for (int p=0;p<4;p++){
                                ull bv=*(const ull*)&A[4096+k*16+2*(nh*4+p)];
                                fma2(m4[p],bv,wd);
                            }
                        }
                        #pragma unroll
                        for (int p=0;p<4;p++) P[(ks*128+lt)*8+(nh*4+p)]=m4[p];
                    }
                    __syncthreads();
                    // reduce -> sp (A[6144..8192))
                    {
                        float ax=0.f, ay=0.f;
                        #pragma unroll
                        for (int q=0;q<4;q++){ float2 t=f2up(P[(q*128+lt)*8+hk]); ax+=t.x; ay+=t.y; }
                        *(ull*)&A[6144+lt*16+2*hk]=
                            f2pk(fmaxf(ax+mb,0.f)*wm, fmaxf(ay+mb,0.f)*wm);
                    }
                    __syncthreads();
                    // dot
                    {
                        int j=tid>>6, seg=tid&63;
                        Pf[tid]=A[6144+(seg*2)*16+j]+A[6144+(seg*2+1)*16+j];
                    }
                    __syncthreads();
                    if (tid<16 && I[tid]>=0){
                        float s=0.f;
                        for (int seg=0;seg<64;seg++) s+=Pf[tid*64+seg];
                        g_score[I[tid]]=s+m2bv;
                    }
                    __syncthreads();
                } else {
                    // l==0 only: score touched non-gated (boundary) nodes
                    if (tid<16){
                        int node=-1;
                        if (tid<nt_old){
                            int nd=g_touchedlist[tid];
                            if (g_outdeg[nd]==0) node=nd;
                        }
                        I[tid]=node;
                    }
                    __syncthreads();
                    for (int jj=0;jj<2;jj++){
                        int j=hk*2+jj, node=I[j];
                        A[lt*16+j]=(node>=0)? g_hidden[node*Dd+lt]:0.f;
                    }
                    __syncthreads();
                    ull aa=0ull;
                    #pragma unroll 4
                    for (int k=0;k<Dd;k++)
                        fma2(aa,*(const ull*)&A[k*16+2*hk],f2dup(linW[k*Dd+lt]));
                    {
                        float2 a=f2up(aa);
                        int na=I[2*hk], nb=I[2*hk+1];
                        float rA=(na>=0)? g_relc[(na/Nn)*Dd+lt]:0.f;
                        float rB=(nb>=0)? g_relc[(nb/Nn)*Dd+lt]:0.f;
                        *(ull*)&A[2048+lt*16+2*hk]=
                            f2pk((a.x+rA)*A[lt*16+2*hk],(a.y+rB)*A[lt*16+2*hk+1]);
                    }
                    __syncthreads();
                    ull hh=0ull;
                    #pragma unroll 4
                    for (int k=0;k<Dd;k++)
                        fma2(hh,*(const ull*)&A[2048+k*16+2*hk],f2dup(m1W[k*Dd+lt]));
                    {
                        float2 h=f2up(hh);
                        *(ull*)&A[4096+lt*16+2*hk]=
                            f2pk(fmaxf(h.x+mb,0.f)*wm, fmaxf(h.y+mb,0.f)*wm);
                    }
                    __syncthreads();
                    {
                        int j=tid>>6, seg=tid&63;
                        Pf[tid]=A[4096+(seg*2)*16+j]+A[4096+(seg*2+1)*16+j];
                    }
                    __syncthreads();
                    if (tid<16 && I[tid]>=0){
                        float s=0.f;
                        for (int seg=0;seg<64;seg++) s+=Pf[tid*64+seg];
                        g_score[I[tid]]=s+m2bv;
                    }
                    __syncthreads();
                }
            }
        }
        GRIDBAR();
    }

    if (bid==0 && tid<Bq*NEGq)
        out[tid] = g_score[g_tgather[tid]];

    #undef GRIDBAR
}

extern "C" void kernel_launch(void* const* d_in, const int* in_sizes, int n_in,
                              void* d_out, int out_size){
    (void)in_sizes; (void)n_in; (void)out_size;
    cudaFuncSetAttribute(k_mega, cudaFuncAttributeMaxDynamicSharedMemorySize, SMEMSZ);
    k_barinit<<<1,1>>>();
    k_mega<<<GRID, TPB, SMEMSZ>>>(
        (const int*)d_in[0], (const int*)d_in[1], (const int*)d_in[2],
        (const float*)d_in[3], (const int*)d_in[4], (const float*)d_in[5],
        (const float*)d_in[6], (const float*)d_in[7],
        (const float*)d_in[8], (const float*)d_in[9],
        (const float*)d_in[10], (const float*)d_in[11],
        (const float*)d_in[12], (const float*)d_in[13],
        (const float*)d_in[14], (const float*)d_in[15],
        (const float*)d_in[16], (const float*)d_in[17],
        (float*)d_out);
}